// round 9
// baseline (speedup 1.0000x reference)
#include <cuda_runtime.h>
#include <cuda_fp16.h>
#include <cstdint>

// ---------------- problem dims --------------------------------------------
#define Bb   8
#define Nn   8192
#define Mm   64
#define KQ   3
#define KN   (KQ*Nn)        // 24576
#define PTOT (Bb*KN)        // 196608
#define SOMK 9
#define QTOT (Bb*Mm*SOMK)   // 4608
#define RTOT (Bb*Mm)        // 512
#define EPSF 1e-5f
#define K_AUG 448           // 387 padded to mult of 64
#define K_FIN 576           // 515 padded to mult of 64

// ---------------- scratch (device globals; no allocation) -----------------
__device__ __half g_h02[(size_t)320*PTOT];   // rows 0..63 = h0, 64..319 = h2
__device__ __half g_h1[(size_t)128*PTOT];
__device__ int    g_seg[PTOT];
__device__ float  g_cnt[Bb*Mm];
__device__ float  g_sum[Bb*3*Mm];
__device__ float  g_cmean[Bb*3*Mm];
__device__ float  g_center[Bb*3*Mm];
__device__ float  g_nodeMax[RTOT*384];
__device__ float  g_first0[Bb*384];
__device__ __half g_aug[(size_t)K_AUG*QTOT];
__device__ __half g_g1[(size_t)512*QTOT];
__device__ __half g_g2[(size_t)512*QTOT];
__device__ __half g_finin[(size_t)K_FIN*RTOT];
__device__ __half g_f1[(size_t)768*RTOT];
__device__ float  g_f2[(size_t)1024*RTOT];
__device__ __half g_w1[128*64];
__device__ __half g_w2[256*128];
__device__ __half g_w3[384*320];
__device__ __half g_kw0[512*K_AUG];
__device__ __half g_kw1[512*512];
__device__ __half g_fw0[768*K_FIN];
__device__ __half g_fw1[1024*768];

// ---------------- PTX helpers ---------------------------------------------
__device__ __forceinline__ uint32_t smem_u32(const void* p) {
    uint32_t a;
    asm("{ .reg .u64 t; cvta.to.shared.u64 t, %1; cvt.u32.u64 %0, t; }" : "=r"(a) : "l"(p));
    return a;
}
#define CPA16(dst, src) \
    asm volatile("cp.async.cg.shared.global [%0], [%1], 16;" :: "r"(dst), "l"(src))
#define CPA_COMMIT() asm volatile("cp.async.commit_group;" ::: "memory")
#define CPA_WAIT(n)  asm volatile("cp.async.wait_group %0;" :: "n"(n) : "memory")

#define LDSM4(r0,r1,r2,r3,addr) \
    asm volatile("ldmatrix.sync.aligned.m8n8.x4.shared.b16 {%0,%1,%2,%3}, [%4];" \
        : "=r"(r0), "=r"(r1), "=r"(r2), "=r"(r3) : "r"(addr))
#define LDSM4T(r0,r1,r2,r3,addr) \
    asm volatile("ldmatrix.sync.aligned.m8n8.x4.trans.shared.b16 {%0,%1,%2,%3}, [%4];" \
        : "=r"(r0), "=r"(r1), "=r"(r2), "=r"(r3) : "r"(addr))

__device__ __forceinline__ void mma16816(float c[4], uint32_t a0, uint32_t a1,
                                         uint32_t a2, uint32_t a3,
                                         uint32_t b0, uint32_t b1) {
    asm volatile(
        "mma.sync.aligned.m16n8k16.row.col.f32.f16.f16.f32 "
        "{%0,%1,%2,%3}, {%4,%5,%6,%7}, {%8,%9}, {%0,%1,%2,%3};"
        : "+f"(c[0]), "+f"(c[1]), "+f"(c[2]), "+f"(c[3])
        : "r"(a0), "r"(a1), "r"(a2), "r"(a3), "r"(b0), "r"(b1));
}

#define APITCH 72                 // halves per A smem row (144 B)
#define A_STG (128*APITCH*2)      // 18432 B per 128-row x 64-k A tile
#define B_STG (64*128*2)          // 16384 B per 64-k x 128-n B tile
#define SMEM_BASE (2*A_STG + 2*B_STG)          // 69632
#define SMEM_SEG  (SMEM_BASE + 64*128*4)       // + 32768 = 102400
#define SMEM_G2F  (A_STG + B_STG)              // 34816 (single-stage fused gemm2)

// ---------------- weight prep + zero (merged) -------------------------------
#define WTOT (128*64 + 256*128 + 384*320 + 512*K_AUG + 512*512 + 768*K_FIN + 1024*768)
#define PREP_TOT (WTOT + RTOT*384 + Bb*Mm + Bb*3*Mm)
__global__ void k_wprep(const float* __restrict__ w1, const float* __restrict__ w2,
                        const float* __restrict__ w3, const float* __restrict__ kw0,
                        const float* __restrict__ kw1, const float* __restrict__ fw0,
                        const float* __restrict__ fw1) {
    int i = blockIdx.x*blockDim.x + threadIdx.x;
    if (i < 128*64)  { g_w1[i] = __float2half_rn(w1[i]); return; }  i -= 128*64;
    if (i < 256*128) { g_w2[i] = __float2half_rn(w2[i]); return; }  i -= 256*128;
    if (i < 384*320) { g_w3[i] = __float2half_rn(w3[i]); return; }  i -= 384*320;
    if (i < 512*K_AUG) { int r = i/K_AUG, c = i%K_AUG;
        g_kw0[i] = (c < 387) ? __float2half_rn(kw0[r*387 + c]) : __half(0.f); return; }
    i -= 512*K_AUG;
    if (i < 512*512) { g_kw1[i] = __float2half_rn(kw1[i]); return; }  i -= 512*512;
    if (i < 768*K_FIN) { int r = i/K_FIN, c = i%K_FIN;
        g_fw0[i] = (c < 515) ? __float2half_rn(fw0[r*515 + c]) : __half(0.f); return; }
    i -= 768*K_FIN;
    if (i < 1024*768) { g_fw1[i] = __float2half_rn(fw1[i]); return; }  i -= 1024*768;
    if (i < RTOT*384) { g_nodeMax[i] = 0.f; return; }  i -= RTOT*384;
    if (i < Bb*Mm)    { g_cnt[i] = 0.f; return; }      i -= Bb*Mm;
    if (i < Bb*3*Mm)  g_sum[i] = 0.f;
}

// ---------------- step 1: top-3 assignment + seg sums ----------------------
__global__ void k_assign(const float* __restrict__ x, const float* __restrict__ node) {
    int b  = blockIdx.y;
    int n  = blockIdx.x*blockDim.x + threadIdx.x;
    int tid = threadIdx.x;
    __shared__ float snode[3][Mm];
    __shared__ float scnt[Mm];
    __shared__ float ssum[3][Mm];
    if (tid < 3*Mm) { int c = tid/Mm, m = tid%Mm; snode[c][m] = node[(b*3+c)*Mm+m]; }
    if (tid < Mm)   scnt[tid] = 0.f;
    if (tid < 3*Mm) ((float*)ssum)[tid] = 0.f;
    __syncthreads();

    float x0 = x[(b*3+0)*Nn+n], x1 = x[(b*3+1)*Nn+n], x2 = x[(b*3+2)*Nn+n];
    float d0 = 1e30f, d1 = 1e30f, d2 = 1e30f;
    int   i0 = 0, i1 = 0, i2 = 0;
    #pragma unroll 8
    for (int m = 0; m < Mm; m++) {
        float dx = x0 - snode[0][m], dy = x1 - snode[1][m], dz = x2 - snode[2][m];
        float d = dx*dx + dy*dy + dz*dz;
        if (d < d2) {
            if (d < d1) {
                if (d < d0) { d2=d1; i2=i1; d1=d0; i1=i0; d0=d; i0=m; }
                else        { d2=d1; i2=i1; d1=d;  i1=m; }
            } else          { d2=d;  i2=m; }
        }
    }
    g_seg[b*KN + 0*Nn + n] = b*Mm + i0;
    g_seg[b*KN + 1*Nn + n] = b*Mm + i1;
    g_seg[b*KN + 2*Nn + n] = b*Mm + i2;

    atomicAdd(&scnt[i0], 1.f); atomicAdd(&scnt[i1], 1.f); atomicAdd(&scnt[i2], 1.f);
    atomicAdd(&ssum[0][i0], x0); atomicAdd(&ssum[1][i0], x1); atomicAdd(&ssum[2][i0], x2);
    atomicAdd(&ssum[0][i1], x0); atomicAdd(&ssum[1][i1], x1); atomicAdd(&ssum[2][i1], x2);
    atomicAdd(&ssum[0][i2], x0); atomicAdd(&ssum[1][i2], x1); atomicAdd(&ssum[2][i2], x2);
    __syncthreads();
    if (tid < Mm)   atomicAdd(&g_cnt[b*Mm+tid], scnt[tid]);
    if (tid < 3*Mm) { int c = tid/Mm, m = tid%Mm; atomicAdd(&g_sum[(b*3+c)*Mm+m], ssum[c][m]); }
}

__global__ void k_mean() {
    int i = blockIdx.x*blockDim.x + threadIdx.x;
    if (i >= Bb*3*Mm) return;
    int m = i % Mm; int b = (i/Mm)/3;
    g_cmean[i] = g_sum[i] / (g_cnt[b*Mm+m] + EPSF);
}

// ---------------- fused gemm2: l0 (h0) + h1 = relu(W1 @ h0 + b1) -----------
// One CTA = 128 points. h0 computed in-kernel -> smem B tile + global h0.
__global__ __launch_bounds__(256, 2)
void k_gemm2f(const float* __restrict__ x, const float* __restrict__ sn,
              const float* __restrict__ w0, const float* __restrict__ b0,
              const float* __restrict__ b1) {
    extern __shared__ __align__(1024) char dsm[];
    const uint32_t base = smem_u32(dsm);
    const uint32_t sA = base;
    const uint32_t sB = base + A_STG;
    const int tid  = threadIdx.x;
    const int lane = tid & 31, warp = tid >> 5;
    const int wm = warp & 3, wn = warp >> 2;
    const int pBase = blockIdx.x * 128;

    // A = W1 (128x64) via cp.async (overlaps with h0 compute below)
    #pragma unroll
    for (int i = 0; i < 4; i++) {
        int e = tid + i*256; int r = e >> 3, c = e & 7;
        CPA16(sA + (uint32_t)(r*APITCH*2 + c*16),
              (const char*)(g_w1 + (size_t)r*64 + c*8));
    }
    CPA_COMMIT();

    // h0: 2 threads per point, 32 channels each (same math as validated k_l0)
    {
        int pt = tid >> 1, hf = tid & 1;
        int p = pBase + pt;
        int n = p % Nn; int b = p / KN;
        int nm = g_seg[p] % Mm;
        float in[6];
        #pragma unroll
        for (int c = 0; c < 3; c++) {
            in[c]   = x[(b*3+c)*Nn+n] - g_cmean[(b*3+c)*Mm+nm];
            in[3+c] = sn[(b*3+c)*Nn+n];
        }
        #pragma unroll
        for (int oi = 0; oi < 32; oi++) {
            int o = hf*32 + oi;
            float a = b0[o];
            #pragma unroll
            for (int c = 0; c < 6; c++) a += w0[o*6+c]*in[c];
            __half hv = __float2half_rn(fmaxf(a, 0.f));
            g_h02[(size_t)o*PTOT + p] = hv;                    // global h0 (for gemm4)
            uint32_t off = (uint32_t)(o*256 + pt*2) ^ (((uint32_t)(o & 7)) << 4);
            *(__half*)(dsm + A_STG + off) = hv;                // smem B tile (k=o)
        }
    }
    CPA_WAIT(0);
    __syncthreads();

    float acc[2][8][4];
    #pragma unroll
    for (int i = 0; i < 2; i++)
        #pragma unroll
        for (int j = 0; j < 8; j++)
            #pragma unroll
            for (int l = 0; l < 4; l++) acc[i][j][l] = 0.f;

    const int mat = lane >> 3, r8 = lane & 7;
    #pragma unroll
    for (int ks = 0; ks < 4; ks++) {
        int kk = ks * 16;
        uint32_t aF[2][4];
        #pragma unroll
        for (int mt = 0; mt < 2; mt++) {
            int row = wm*32 + mt*16 + r8 + ((mat & 1) << 3);
            int kof = kk + ((mat >> 1) << 3);
            LDSM4(aF[mt][0], aF[mt][1], aF[mt][2], aF[mt][3],
                  sA + (uint32_t)(row*APITCH*2 + kof*2));
        }
        uint32_t bF[4][4];
        #pragma unroll
        for (int q = 0; q < 4; q++) {
            int k = kk + r8 + ((mat & 1) << 3);
            int n = wn*64 + q*16 + ((mat >> 1) << 3);
            uint32_t off = (uint32_t)(k*256 + n*2);
            off ^= ((uint32_t)(k & 7)) << 4;
            LDSM4T(bF[q][0], bF[q][1], bF[q][2], bF[q][3], sB + off);
        }
        #pragma unroll
        for (int nt = 0; nt < 8; nt++) {
            uint32_t b0f = bF[nt >> 1][(nt & 1)*2];
            uint32_t b1f = bF[nt >> 1][(nt & 1)*2 + 1];
            #pragma unroll
            for (int mt = 0; mt < 2; mt++)
                mma16816(acc[mt][nt], aF[mt][0], aF[mt][1], aF[mt][2], aF[mt][3], b0f, b1f);
        }
    }

    #pragma unroll
    for (int mt = 0; mt < 2; mt++) {
        int r0 = wm*32 + mt*16 + (lane >> 2);
        float bv0 = b1[r0], bv1 = b1[r0 + 8];
        #pragma unroll
        for (int nt = 0; nt < 8; nt++) {
            int n0 = pBase + wn*64 + nt*8 + 2*(lane & 3);
            float v00 = fmaxf(acc[mt][nt][0] + bv0, 0.f);
            float v01 = fmaxf(acc[mt][nt][1] + bv0, 0.f);
            float v10 = fmaxf(acc[mt][nt][2] + bv1, 0.f);
            float v11 = fmaxf(acc[mt][nt][3] + bv1, 0.f);
            *(__half2*)&g_h1[(size_t)r0*PTOT + n0]       = __floats2half2_rn(v00, v01);
            *(__half2*)&g_h1[(size_t)(r0 + 8)*PTOT + n0] = __floats2half2_rn(v10, v11);
        }
    }
}

// ---------------- fp16 HMMA GEMM, BK=64 ------------------------------------
// OUT=0: fp16 C; OUT=1: fp32 C; OUT=2: smem segment-max + single flush.
template<int OUT, int NX>
__global__ __launch_bounds__(256, 2)
void k_hgemm(const __half* __restrict__ A, const __half* __restrict__ Bm,
             const float* __restrict__ bias, void* __restrict__ C,
             int Nd, int Kd) {
    extern __shared__ __align__(1024) char dsm[];
    const uint32_t base = smem_u32(dsm);
    const uint32_t sA[2] = { base,            base + A_STG };
    const uint32_t sB[2] = { base + 2*A_STG,  base + 2*A_STG + B_STG };
    float* smax = (float*)(dsm + SMEM_BASE);

    const int tid  = threadIdx.x;
    const int lane = tid & 31, warp = tid >> 5;
    const int wm = warp & 3, wn = warp >> 2;
    const int rowBase = blockIdx.y * 128;
    const int colBase = blockIdx.x * (128*NX);
    const int nT = Kd / 64;
    const __half* Arow = A + (size_t)rowBase*Kd;

    if (OUT == 2) {
        for (int i = tid; i < 64*128; i += 256) smax[i] = 0.f;
        __syncthreads();
    }

    for (int nx = 0; nx < NX; nx++) {
        const int cb = colBase + nx*128;
        const __half* Brow = Bm + cb;

        float acc[2][8][4];
        #pragma unroll
        for (int i = 0; i < 2; i++)
            #pragma unroll
            for (int j = 0; j < 8; j++)
                #pragma unroll
                for (int l = 0; l < 4; l++) acc[i][j][l] = 0.f;

        auto loadStage = [&](int t, int s) {
            #pragma unroll
            for (int i = 0; i < 4; i++) {
                int e = tid + i*256; int r = e >> 3, c = e & 7;
                CPA16(sA[s] + (uint32_t)(r*APITCH*2 + c*16),
                      (const char*)(Arow + (size_t)r*Kd + t*64 + c*8));
            }
            #pragma unroll
            for (int i = 0; i < 4; i++) {
                int e = tid + i*256; int k = e >> 4, c = e & 15;
                uint32_t off = (uint32_t)(k*256 + c*16);
                off ^= ((uint32_t)(k & 7)) << 4;
                CPA16(sB[s] + off, (const char*)(Brow + (size_t)(t*64 + k)*Nd + c*8));
            }
        };

        loadStage(0, 0); CPA_COMMIT();
        for (int t = 0; t < nT; t++) {
            if (t + 1 < nT) { loadStage(t + 1, (t + 1) & 1); CPA_COMMIT(); CPA_WAIT(1); }
            else            { CPA_WAIT(0); }
            __syncthreads();
            int buf = t & 1;
            #pragma unroll
            for (int ks = 0; ks < 4; ks++) {
                int kk = ks * 16;
                int mat = lane >> 3, r8 = lane & 7;
                uint32_t aF[2][4];
                #pragma unroll
                for (int mt = 0; mt < 2; mt++) {
                    int row = wm*32 + mt*16 + r8 + ((mat & 1) << 3);
                    int kof = kk + ((mat >> 1) << 3);
                    LDSM4(aF[mt][0], aF[mt][1], aF[mt][2], aF[mt][3],
                          sA[buf] + (uint32_t)(row*APITCH*2 + kof*2));
                }
                uint32_t bF[4][4];
                #pragma unroll
                for (int q = 0; q < 4; q++) {
                    int k = kk + r8 + ((mat & 1) << 3);
                    int n = wn*64 + q*16 + ((mat >> 1) << 3);
                    uint32_t off = (uint32_t)(k*256 + n*2);
                    off ^= ((uint32_t)(k & 7)) << 4;
                    LDSM4T(bF[q][0], bF[q][1], bF[q][2], bF[q][3], sB[buf] + off);
                }
                #pragma unroll
                for (int nt = 0; nt < 8; nt++) {
                    uint32_t b0 = bF[nt >> 1][(nt & 1)*2];
                    uint32_t b1 = bF[nt >> 1][(nt & 1)*2 + 1];
                    #pragma unroll
                    for (int mt = 0; mt < 2; mt++)
                        mma16816(acc[mt][nt], aF[mt][0], aF[mt][1], aF[mt][2], aF[mt][3], b0, b1);
                }
            }
            __syncthreads();
        }

        #pragma unroll
        for (int mt = 0; mt < 2; mt++) {
            int lr0 = wm*32 + mt*16 + (lane >> 2);
            int r0 = rowBase + lr0;
            float bv0 = bias[r0], bv1 = bias[r0 + 8];
            #pragma unroll
            for (int nt = 0; nt < 8; nt++) {
                int n0 = cb + wn*64 + nt*8 + 2*(lane & 3);
                float v00 = fmaxf(acc[mt][nt][0] + bv0, 0.f);
                float v01 = fmaxf(acc[mt][nt][1] + bv0, 0.f);
                float v10 = fmaxf(acc[mt][nt][2] + bv1, 0.f);
                float v11 = fmaxf(acc[mt][nt][3] + bv1, 0.f);
                if (OUT == 0) {
                    __half* Ch = (__half*)C;
                    *(__half2*)&Ch[(size_t)r0*Nd + n0]       = __floats2half2_rn(v00, v01);
                    *(__half2*)&Ch[(size_t)(r0 + 8)*Nd + n0] = __floats2half2_rn(v10, v11);
                } else if (OUT == 1) {
                    float* Cf = (float*)C;
                    *(float2*)&Cf[(size_t)r0*Nd + n0]       = make_float2(v00, v01);
                    *(float2*)&Cf[(size_t)(r0 + 8)*Nd + n0] = make_float2(v10, v11);
                } else {
                    int s0 = g_seg[n0] & 63, s1 = g_seg[n0 + 1] & 63;
                    atomicMax((int*)&smax[s0*128 + lr0],     __float_as_int(v00));
                    atomicMax((int*)&smax[s1*128 + lr0],     __float_as_int(v01));
                    atomicMax((int*)&smax[s0*128 + lr0 + 8], __float_as_int(v10));
                    atomicMax((int*)&smax[s1*128 + lr0 + 8], __float_as_int(v11));
                    if ((n0 % KN) == 0) {
                        g_first0[(n0/KN)*384 + r0]     = v00;
                        g_first0[(n0/KN)*384 + r0 + 8] = v10;
                    }
                }
            }
        }
        if (OUT == 2) __syncthreads();
    }

    if (OUT == 2) {
        int bIdx = colBase / KN;
        for (int i = tid; i < 64*128; i += 256) {
            float v = smax[i];
            if (v > 0.f) {
                int node = i >> 7, lr = i & 127;
                atomicMax((int*)&g_nodeMax[(size_t)(bIdx*Mm + node)*384 + rowBase + lr],
                          __float_as_int(v));
            }
        }
    }
}

// ---------------- KNN module prep ------------------------------------------
__global__ void k_center(const int* __restrict__ I) {
    int i = blockIdx.x*blockDim.x + threadIdx.x;
    if (i >= Bb*3*Mm) return;
    int m = i % Mm; int bc = i / Mm; int b = bc/3; int c = bc%3;
    float s = 0.f;
    #pragma unroll
    for (int kk = 0; kk < SOMK; kk++) {
        int im = I[(b*Mm+m)*SOMK + kk];
        s += g_cmean[(b*3+c)*Mm + im];
    }
    g_center[i] = s * (1.0f/SOMK);
}

__global__ void k_aug(const int* __restrict__ I) {
    int t = blockIdx.x*blockDim.x + threadIdx.x;
    if (t >= K_AUG*QTOT) return;
    int q = t % QTOT, c = t / QTOT;
    float v = 0.f;
    if (c < 387) {
        int kk = q % SOMK; int bm = q / SOMK; int b = bm / Mm; int m = bm % Mm;
        int im = I[bm*SOMK + kk];
        if (c < 3)
            v = g_cmean[(b*3+c)*Mm + im] - g_center[(b*3+c)*Mm + m];
        else
            v = (g_cnt[b*Mm+im] > 0.f) ? g_nodeMax[(size_t)(b*Mm+im)*384 + (c-3)]
                                       : g_first0[b*384 + (c-3)];
    }
    g_aug[t] = __float2half_rn(v);
}

__global__ void k_finin() {
    int t = blockIdx.x*blockDim.x + threadIdx.x;
    if (t >= K_FIN*RTOT) return;
    int r = t % RTOT, c = t / RTOT;
    float v = 0.f;
    if (c < 3) {
        int b = r / Mm, m = r % Mm;
        v = g_center[(b*3+c)*Mm + m];
    } else if (c < 515) {
        float mx = -1e30f;
        size_t base = (size_t)(c-3)*QTOT + (size_t)r*SOMK;
        #pragma unroll
        for (int kk = 0; kk < SOMK; kk++) mx = fmaxf(mx, __half2float(g_g2[base+kk]));
        v = mx;
    }
    g_finin[t] = __float2half_rn(v);
}

__global__ void k_out(float* __restrict__ out) {
    int t = blockIdx.x*blockDim.x + threadIdx.x;
    if (t >= Bb*1024) return;
    int c = t % 1024, b = t / 1024;
    float mx = -1e30f;
    #pragma unroll 8
    for (int m = 0; m < Mm; m++) mx = fmaxf(mx, g_f2[(size_t)c*RTOT + b*Mm + m]);
    out[t] = mx;
}

// ---------------- launch ----------------------------------------------------
extern "C" void kernel_launch(void* const* d_in, const int* in_sizes, int n_in,
                              void* d_out, int out_size) {
    const float* x      = (const float*)d_in[0];
    const float* sn     = (const float*)d_in[1];
    const float* node   = (const float*)d_in[2];
    const int*   knnI   = (const int*)  d_in[3];
    const float* pr_w0  = (const float*)d_in[4];
    const float* pr_b0  = (const float*)d_in[5];
    const float* pr_b1  = (const float*)d_in[7];
    const float* pr_b2  = (const float*)d_in[9];
    const float* pr_b3  = (const float*)d_in[11];
    const float* knn_b0 = (const float*)d_in[13];
    const float* knn_b1 = (const float*)d_in[15];
    const float* fin_b0 = (const float*)d_in[17];
    const float* fin_b1 = (const float*)d_in[19];
    float* out = (float*)d_out;

    __half *p_h02, *p_h1, *p_aug, *p_g1, *p_g2, *p_finin, *p_f1;
    __half *p_w2, *p_w3, *p_kw0, *p_kw1, *p_fw0, *p_fw1;
    float  *p_f2;
    cudaGetSymbolAddress((void**)&p_h02,   g_h02);
    cudaGetSymbolAddress((void**)&p_h1,    g_h1);
    cudaGetSymbolAddress((void**)&p_aug,   g_aug);
    cudaGetSymbolAddress((void**)&p_g1,    g_g1);
    cudaGetSymbolAddress((void**)&p_g2,    g_g2);
    cudaGetSymbolAddress((void**)&p_finin, g_finin);
    cudaGetSymbolAddress((void**)&p_f1,    g_f1);
    cudaGetSymbolAddress((void**)&p_f2,    g_f2);
    cudaGetSymbolAddress((void**)&p_w2,    g_w2);
    cudaGetSymbolAddress((void**)&p_w3,    g_w3);
    cudaGetSymbolAddress((void**)&p_kw0,   g_kw0);
    cudaGetSymbolAddress((void**)&p_kw1,   g_kw1);
    cudaGetSymbolAddress((void**)&p_fw0,   g_fw0);
    cudaGetSymbolAddress((void**)&p_fw1,   g_fw1);

    cudaFuncSetAttribute(k_gemm2f,     cudaFuncAttributeMaxDynamicSharedMemorySize, SMEM_G2F);
    cudaFuncSetAttribute(k_hgemm<0,1>, cudaFuncAttributeMaxDynamicSharedMemorySize, SMEM_BASE);
    cudaFuncSetAttribute(k_hgemm<1,1>, cudaFuncAttributeMaxDynamicSharedMemorySize, SMEM_BASE);
    cudaFuncSetAttribute(k_hgemm<2,8>, cudaFuncAttributeMaxDynamicSharedMemorySize, SMEM_SEG);

    k_wprep<<<(PREP_TOT + 255)/256, 256>>>(
        (const float*)d_in[6], (const float*)d_in[8], (const float*)d_in[10],
        (const float*)d_in[12], (const float*)d_in[14],
        (const float*)d_in[16], (const float*)d_in[18]);

    k_assign<<<dim3(Nn/256, Bb), 256>>>(x, node);
    k_mean  <<<(Bb*3*Mm + 255)/256, 256>>>();

    // PointResNet: fused l0+gemm2, then gemm3, then gemm4+segmax
    k_gemm2f<<<PTOT/128, 256, SMEM_G2F>>>(x, sn, pr_w0, pr_b0, pr_b1);
    k_hgemm<0,1><<<dim3(PTOT/128, 2), 256, SMEM_BASE>>>(p_w2, p_h1, pr_b2, p_h02 + (size_t)64*PTOT, PTOT, 128);
    k_hgemm<2,8><<<dim3(PTOT/1024, 3), 256, SMEM_SEG>>>(p_w3, p_h02, pr_b3, nullptr, PTOT, 320);

    // KNN module over SOM nodes
    k_center<<<(Bb*3*Mm + 255)/256, 256>>>(knnI);
    k_aug   <<<(K_AUG*QTOT + 255)/256, 256>>>(knnI);
    k_hgemm<0,1><<<dim3(QTOT/128, 4), 256, SMEM_BASE>>>(p_kw0, p_aug, knn_b0, p_g1, QTOT, K_AUG);
    k_hgemm<0,1><<<dim3(QTOT/128, 4), 256, SMEM_BASE>>>(p_kw1, p_g1,  knn_b1, p_g2, QTOT, 512);

    // final PointNet + global max
    k_finin<<<(K_FIN*RTOT + 255)/256, 256>>>();
    k_hgemm<0,1><<<dim3(RTOT/128, 6), 256, SMEM_BASE>>>(p_fw0, p_finin, fin_b0, p_f1, RTOT, K_FIN);
    k_hgemm<1,1><<<dim3(RTOT/128, 8), 256, SMEM_BASE>>>(p_fw1, p_f1,    fin_b1, p_f2, RTOT, 768);
    k_out<<<(Bb*1024 + 255)/256, 256>>>(out);
}

// round 10
// speedup vs baseline: 1.0430x; 1.0430x over previous
#include <cuda_runtime.h>
#include <cuda_fp16.h>
#include <cstdint>

// ---------------- problem dims --------------------------------------------
#define Bb   8
#define Nn   8192
#define Mm   64
#define KQ   3
#define KN   (KQ*Nn)        // 24576
#define PTOT (Bb*KN)        // 196608
#define SOMK 9
#define QTOT (Bb*Mm*SOMK)   // 4608
#define RTOT (Bb*Mm)        // 512
#define EPSF 1e-5f
#define K_AUG 448           // 387 padded to mult of 64
#define K_FIN 576           // 515 padded to mult of 64

// ---------------- scratch (device globals; no allocation) -----------------
__device__ __half g_h02[(size_t)320*PTOT];   // rows 0..63 = h0, 64..319 = h2
__device__ __half g_h1[(size_t)128*PTOT];
__device__ int    g_seg[PTOT];
__device__ float  g_cnt[Bb*Mm];
__device__ float  g_sum[Bb*3*Mm];
__device__ float  g_cmean[Bb*3*Mm];
__device__ float  g_center[Bb*3*Mm];
__device__ float  g_nodeMax[RTOT*384];
__device__ float  g_first0[Bb*384];
__device__ __half g_aug[(size_t)K_AUG*QTOT];
__device__ __half g_g1[(size_t)512*QTOT];
__device__ __half g_g2[(size_t)512*QTOT];
__device__ __half g_finin[(size_t)K_FIN*RTOT];
__device__ __half g_f1[(size_t)768*RTOT];
__device__ __half g_w1[128*64];
__device__ __half g_w2[256*128];
__device__ __half g_w3[384*320];
__device__ __half g_kw0[512*K_AUG];
__device__ __half g_kw1[512*512];
__device__ __half g_fw0[768*K_FIN];
__device__ __half g_fw1[1024*768];

// ---------------- PTX helpers ---------------------------------------------
__device__ __forceinline__ uint32_t smem_u32(const void* p) {
    uint32_t a;
    asm("{ .reg .u64 t; cvta.to.shared.u64 t, %1; cvt.u32.u64 %0, t; }" : "=r"(a) : "l"(p));
    return a;
}
#define CPA16(dst, src) \
    asm volatile("cp.async.cg.shared.global [%0], [%1], 16;" :: "r"(dst), "l"(src))
#define CPA_COMMIT() asm volatile("cp.async.commit_group;" ::: "memory")
#define CPA_WAIT(n)  asm volatile("cp.async.wait_group %0;" :: "n"(n) : "memory")

#define LDSM4(r0,r1,r2,r3,addr) \
    asm volatile("ldmatrix.sync.aligned.m8n8.x4.shared.b16 {%0,%1,%2,%3}, [%4];" \
        : "=r"(r0), "=r"(r1), "=r"(r2), "=r"(r3) : "r"(addr))
#define LDSM4T(r0,r1,r2,r3,addr) \
    asm volatile("ldmatrix.sync.aligned.m8n8.x4.trans.shared.b16 {%0,%1,%2,%3}, [%4];" \
        : "=r"(r0), "=r"(r1), "=r"(r2), "=r"(r3) : "r"(addr))

__device__ __forceinline__ void mma16816(float c[4], uint32_t a0, uint32_t a1,
                                         uint32_t a2, uint32_t a3,
                                         uint32_t b0, uint32_t b1) {
    asm volatile(
        "mma.sync.aligned.m16n8k16.row.col.f32.f16.f16.f32 "
        "{%0,%1,%2,%3}, {%4,%5,%6,%7}, {%8,%9}, {%0,%1,%2,%3};"
        : "+f"(c[0]), "+f"(c[1]), "+f"(c[2]), "+f"(c[3])
        : "r"(a0), "r"(a1), "r"(a2), "r"(a3), "r"(b0), "r"(b1));
}

#define APITCH 72                 // halves per A smem row (144 B)
#define A_STG (128*APITCH*2)      // 18432 B per 128-row x 64-k A tile
#define B_STG (64*128*2)          // 16384 B per 64-k x 128-n B tile
#define SMEM_BASE (2*A_STG + 2*B_STG)          // 69632
#define SMEM_SEG  (SMEM_BASE + 64*128*4)       // + 32768 = 102400

// ---------------- weight prep + zero (merged, also zeroes out) -------------
#define WTOT (128*64 + 256*128 + 384*320 + 512*K_AUG + 512*512 + 768*K_FIN + 1024*768)
#define PREP_TOT (WTOT + RTOT*384 + Bb*Mm + Bb*3*Mm + Bb*1024)
__global__ void k_wprep(const float* __restrict__ w1, const float* __restrict__ w2,
                        const float* __restrict__ w3, const float* __restrict__ kw0,
                        const float* __restrict__ kw1, const float* __restrict__ fw0,
                        const float* __restrict__ fw1, float* __restrict__ out) {
    int i = blockIdx.x*blockDim.x + threadIdx.x;
    if (i < 128*64)  { g_w1[i] = __float2half_rn(w1[i]); return; }  i -= 128*64;
    if (i < 256*128) { g_w2[i] = __float2half_rn(w2[i]); return; }  i -= 256*128;
    if (i < 384*320) { g_w3[i] = __float2half_rn(w3[i]); return; }  i -= 384*320;
    if (i < 512*K_AUG) { int r = i/K_AUG, c = i%K_AUG;
        g_kw0[i] = (c < 387) ? __float2half_rn(kw0[r*387 + c]) : __half(0.f); return; }
    i -= 512*K_AUG;
    if (i < 512*512) { g_kw1[i] = __float2half_rn(kw1[i]); return; }  i -= 512*512;
    if (i < 768*K_FIN) { int r = i/K_FIN, c = i%K_FIN;
        g_fw0[i] = (c < 515) ? __float2half_rn(fw0[r*515 + c]) : __half(0.f); return; }
    i -= 768*K_FIN;
    if (i < 1024*768) { g_fw1[i] = __float2half_rn(fw1[i]); return; }  i -= 1024*768;
    if (i < RTOT*384) { g_nodeMax[i] = 0.f; return; }  i -= RTOT*384;
    if (i < Bb*Mm)    { g_cnt[i] = 0.f; return; }      i -= Bb*Mm;
    if (i < Bb*3*Mm)  { g_sum[i] = 0.f; return; }      i -= Bb*3*Mm;
    if (i < Bb*1024)  out[i] = 0.f;
}

// ---------------- step 1: top-3 assignment + seg sums ----------------------
__global__ void k_assign(const float* __restrict__ x, const float* __restrict__ node) {
    int b  = blockIdx.y;
    int n  = blockIdx.x*blockDim.x + threadIdx.x;
    int tid = threadIdx.x;
    __shared__ float snode[3][Mm];
    __shared__ float scnt[Mm];
    __shared__ float ssum[3][Mm];
    if (tid < 3*Mm) { int c = tid/Mm, m = tid%Mm; snode[c][m] = node[(b*3+c)*Mm+m]; }
    if (tid < Mm)   scnt[tid] = 0.f;
    if (tid < 3*Mm) ((float*)ssum)[tid] = 0.f;
    __syncthreads();

    float x0 = x[(b*3+0)*Nn+n], x1 = x[(b*3+1)*Nn+n], x2 = x[(b*3+2)*Nn+n];
    float d0 = 1e30f, d1 = 1e30f, d2 = 1e30f;
    int   i0 = 0, i1 = 0, i2 = 0;
    #pragma unroll 8
    for (int m = 0; m < Mm; m++) {
        float dx = x0 - snode[0][m], dy = x1 - snode[1][m], dz = x2 - snode[2][m];
        float d = dx*dx + dy*dy + dz*dz;
        if (d < d2) {
            if (d < d1) {
                if (d < d0) { d2=d1; i2=i1; d1=d0; i1=i0; d0=d; i0=m; }
                else        { d2=d1; i2=i1; d1=d;  i1=m; }
            } else          { d2=d;  i2=m; }
        }
    }
    g_seg[b*KN + 0*Nn + n] = b*Mm + i0;
    g_seg[b*KN + 1*Nn + n] = b*Mm + i1;
    g_seg[b*KN + 2*Nn + n] = b*Mm + i2;

    atomicAdd(&scnt[i0], 1.f); atomicAdd(&scnt[i1], 1.f); atomicAdd(&scnt[i2], 1.f);
    atomicAdd(&ssum[0][i0], x0); atomicAdd(&ssum[1][i0], x1); atomicAdd(&ssum[2][i0], x2);
    atomicAdd(&ssum[0][i1], x0); atomicAdd(&ssum[1][i1], x1); atomicAdd(&ssum[2][i1], x2);
    atomicAdd(&ssum[0][i2], x0); atomicAdd(&ssum[1][i2], x1); atomicAdd(&ssum[2][i2], x2);
    __syncthreads();
    if (tid < Mm)   atomicAdd(&g_cnt[b*Mm+tid], scnt[tid]);
    if (tid < 3*Mm) { int c = tid/Mm, m = tid%Mm; atomicAdd(&g_sum[(b*3+c)*Mm+m], ssum[c][m]); }
}

// ---------------- mean + KNN center (single block; center after sync) ------
__global__ void k_meancenter(const int* __restrict__ I) {
    int tid = threadIdx.x;
    for (int i = tid; i < Bb*3*Mm; i += blockDim.x) {
        int m = i % Mm; int b = (i/Mm)/3;
        g_cmean[i] = g_sum[i] / (g_cnt[b*Mm+m] + EPSF);
    }
    __syncthreads();
    for (int i = tid; i < Bb*3*Mm; i += blockDim.x) {
        int m = i % Mm; int bc = i / Mm; int b = bc/3; int c = bc%3;
        float s = 0.f;
        #pragma unroll
        for (int kk = 0; kk < SOMK; kk++) {
            int im = I[(b*Mm+m)*SOMK + kk];
            s += g_cmean[(b*3+c)*Mm + im];
        }
        g_center[i] = s * (1.0f/SOMK);
    }
}

// ---------------- fused layer-0 --------------------------------------------
__global__ void k_l0(const float* __restrict__ x, const float* __restrict__ sn,
                     const float* __restrict__ w0, const float* __restrict__ b0) {
    __shared__ float sw[64*6];
    __shared__ float sb[64];
    int tid = threadIdx.x;
    for (int i = tid; i < 64*6; i += blockDim.x) sw[i] = w0[i];
    if (tid < 64) sb[tid] = b0[tid];
    __syncthreads();
    int p = blockIdx.x*blockDim.x + tid;
    int n = p % Nn; int b = p / KN;
    int nm = g_seg[p] % Mm;
    float in[6];
    #pragma unroll
    for (int c = 0; c < 3; c++) {
        in[c]   = x[(b*3+c)*Nn+n] - g_cmean[(b*3+c)*Mm+nm];
        in[3+c] = sn[(b*3+c)*Nn+n];
    }
    #pragma unroll
    for (int o = 0; o < 64; o++) {
        float a = sb[o];
        #pragma unroll
        for (int c = 0; c < 6; c++) a += sw[o*6+c]*in[c];
        g_h02[(size_t)o*PTOT + p] = __float2half_rn(fmaxf(a, 0.f));
    }
}

// ---------------- fp16 HMMA GEMM, BK=64 ------------------------------------
// OUT=0: fp16 C; OUT=2: smem segment-max + flush; OUT=3: atomicMax into out.
template<int OUT, int NX>
__global__ __launch_bounds__(256, 2)
void k_hgemm(const __half* __restrict__ A, const __half* __restrict__ Bm,
             const float* __restrict__ bias, void* __restrict__ C,
             int Nd, int Kd) {
    extern __shared__ __align__(1024) char dsm[];
    const uint32_t base = smem_u32(dsm);
    const uint32_t sA[2] = { base,            base + A_STG };
    const uint32_t sB[2] = { base + 2*A_STG,  base + 2*A_STG + B_STG };
    float* smax = (float*)(dsm + SMEM_BASE);

    const int tid  = threadIdx.x;
    const int lane = tid & 31, warp = tid >> 5;
    const int wm = warp & 3, wn = warp >> 2;
    const int rowBase = blockIdx.y * 128;
    const int colBase = blockIdx.x * (128*NX);
    const int nT = Kd / 64;
    const __half* Arow = A + (size_t)rowBase*Kd;

    if (OUT == 2) {
        for (int i = tid; i < 64*128; i += 256) smax[i] = 0.f;
        __syncthreads();
    }

    for (int nx = 0; nx < NX; nx++) {
        const int cb = colBase + nx*128;
        const __half* Brow = Bm + cb;

        float acc[2][8][4];
        #pragma unroll
        for (int i = 0; i < 2; i++)
            #pragma unroll
            for (int j = 0; j < 8; j++)
                #pragma unroll
                for (int l = 0; l < 4; l++) acc[i][j][l] = 0.f;

        auto loadStage = [&](int t, int s) {
            #pragma unroll
            for (int i = 0; i < 4; i++) {
                int e = tid + i*256; int r = e >> 3, c = e & 7;
                CPA16(sA[s] + (uint32_t)(r*APITCH*2 + c*16),
                      (const char*)(Arow + (size_t)r*Kd + t*64 + c*8));
            }
            #pragma unroll
            for (int i = 0; i < 4; i++) {
                int e = tid + i*256; int k = e >> 4, c = e & 15;
                uint32_t off = (uint32_t)(k*256 + c*16);
                off ^= ((uint32_t)(k & 7)) << 4;
                CPA16(sB[s] + off, (const char*)(Brow + (size_t)(t*64 + k)*Nd + c*8));
            }
        };

        loadStage(0, 0); CPA_COMMIT();
        for (int t = 0; t < nT; t++) {
            if (t + 1 < nT) { loadStage(t + 1, (t + 1) & 1); CPA_COMMIT(); CPA_WAIT(1); }
            else            { CPA_WAIT(0); }
            __syncthreads();
            int buf = t & 1;
            #pragma unroll
            for (int ks = 0; ks < 4; ks++) {
                int kk = ks * 16;
                int mat = lane >> 3, r8 = lane & 7;
                uint32_t aF[2][4];
                #pragma unroll
                for (int mt = 0; mt < 2; mt++) {
                    int row = wm*32 + mt*16 + r8 + ((mat & 1) << 3);
                    int kof = kk + ((mat >> 1) << 3);
                    LDSM4(aF[mt][0], aF[mt][1], aF[mt][2], aF[mt][3],
                          sA[buf] + (uint32_t)(row*APITCH*2 + kof*2));
                }
                uint32_t bF[4][4];
                #pragma unroll
                for (int q = 0; q < 4; q++) {
                    int k = kk + r8 + ((mat & 1) << 3);
                    int n = wn*64 + q*16 + ((mat >> 1) << 3);
                    uint32_t off = (uint32_t)(k*256 + n*2);
                    off ^= ((uint32_t)(k & 7)) << 4;
                    LDSM4T(bF[q][0], bF[q][1], bF[q][2], bF[q][3], sB[buf] + off);
                }
                #pragma unroll
                for (int nt = 0; nt < 8; nt++) {
                    uint32_t b0 = bF[nt >> 1][(nt & 1)*2];
                    uint32_t b1 = bF[nt >> 1][(nt & 1)*2 + 1];
                    #pragma unroll
                    for (int mt = 0; mt < 2; mt++)
                        mma16816(acc[mt][nt], aF[mt][0], aF[mt][1], aF[mt][2], aF[mt][3], b0, b1);
                }
            }
            __syncthreads();
        }

        #pragma unroll
        for (int mt = 0; mt < 2; mt++) {
            int lr0 = wm*32 + mt*16 + (lane >> 2);
            int r0 = rowBase + lr0;
            float bv0 = bias[r0], bv1 = bias[r0 + 8];
            #pragma unroll
            for (int nt = 0; nt < 8; nt++) {
                int n0 = cb + wn*64 + nt*8 + 2*(lane & 3);
                float v00 = fmaxf(acc[mt][nt][0] + bv0, 0.f);
                float v01 = fmaxf(acc[mt][nt][1] + bv0, 0.f);
                float v10 = fmaxf(acc[mt][nt][2] + bv1, 0.f);
                float v11 = fmaxf(acc[mt][nt][3] + bv1, 0.f);
                if (OUT == 0) {
                    __half* Ch = (__half*)C;
                    *(__half2*)&Ch[(size_t)r0*Nd + n0]       = __floats2half2_rn(v00, v01);
                    *(__half2*)&Ch[(size_t)(r0 + 8)*Nd + n0] = __floats2half2_rn(v10, v11);
                } else if (OUT == 3) {
                    // global max-pool over nodes: out[b*1024 + channel]
                    float* Of = (float*)C;
                    atomicMax((int*)&Of[(n0 >> 6)*1024 + r0],           __float_as_int(v00));
                    atomicMax((int*)&Of[((n0+1) >> 6)*1024 + r0],       __float_as_int(v01));
                    atomicMax((int*)&Of[(n0 >> 6)*1024 + r0 + 8],       __float_as_int(v10));
                    atomicMax((int*)&Of[((n0+1) >> 6)*1024 + r0 + 8],   __float_as_int(v11));
                } else {
                    int s0 = g_seg[n0] & 63, s1 = g_seg[n0 + 1] & 63;
                    atomicMax((int*)&smax[s0*128 + lr0],     __float_as_int(v00));
                    atomicMax((int*)&smax[s1*128 + lr0],     __float_as_int(v01));
                    atomicMax((int*)&smax[s0*128 + lr0 + 8], __float_as_int(v10));
                    atomicMax((int*)&smax[s1*128 + lr0 + 8], __float_as_int(v11));
                    if ((n0 % KN) == 0) {
                        g_first0[(n0/KN)*384 + r0]     = v00;
                        g_first0[(n0/KN)*384 + r0 + 8] = v10;
                    }
                }
            }
        }
        if (OUT == 2) __syncthreads();
    }

    if (OUT == 2) {
        int bIdx = colBase / KN;
        for (int i = tid; i < 64*128; i += 256) {
            float v = smax[i];
            if (v > 0.f) {
                int node = i >> 7, lr = i & 127;
                atomicMax((int*)&g_nodeMax[(size_t)(bIdx*Mm + node)*384 + rowBase + lr],
                          __float_as_int(v));
            }
        }
    }
}

// ---------------- KNN module prep ------------------------------------------
__global__ void k_aug(const int* __restrict__ I) {
    int t = blockIdx.x*blockDim.x + threadIdx.x;
    if (t >= K_AUG*QTOT) return;
    int q = t % QTOT, c = t / QTOT;
    float v = 0.f;
    if (c < 387) {
        int kk = q % SOMK; int bm = q / SOMK; int b = bm / Mm; int m = bm % Mm;
        int im = I[bm*SOMK + kk];
        if (c < 3)
            v = g_cmean[(b*3+c)*Mm + im] - g_center[(b*3+c)*Mm + m];
        else
            v = (g_cnt[b*Mm+im] > 0.f) ? g_nodeMax[(size_t)(b*Mm+im)*384 + (c-3)]
                                       : g_first0[b*384 + (c-3)];
    }
    g_aug[t] = __float2half_rn(v);
}

__global__ void k_finin() {
    int t = blockIdx.x*blockDim.x + threadIdx.x;
    if (t >= K_FIN*RTOT) return;
    int r = t % RTOT, c = t / RTOT;
    float v = 0.f;
    if (c < 3) {
        int b = r / Mm, m = r % Mm;
        v = g_center[(b*3+c)*Mm + m];
    } else if (c < 515) {
        float mx = -1e30f;
        size_t base = (size_t)(c-3)*QTOT + (size_t)r*SOMK;
        #pragma unroll
        for (int kk = 0; kk < SOMK; kk++) mx = fmaxf(mx, __half2float(g_g2[base+kk]));
        v = mx;
    }
    g_finin[t] = __float2half_rn(v);
}

// ---------------- launch ----------------------------------------------------
extern "C" void kernel_launch(void* const* d_in, const int* in_sizes, int n_in,
                              void* d_out, int out_size) {
    const float* x      = (const float*)d_in[0];
    const float* sn     = (const float*)d_in[1];
    const float* node   = (const float*)d_in[2];
    const int*   knnI   = (const int*)  d_in[3];
    const float* pr_w0  = (const float*)d_in[4];
    const float* pr_b0  = (const float*)d_in[5];
    const float* pr_b1  = (const float*)d_in[7];
    const float* pr_b2  = (const float*)d_in[9];
    const float* pr_b3  = (const float*)d_in[11];
    const float* knn_b0 = (const float*)d_in[13];
    const float* knn_b1 = (const float*)d_in[15];
    const float* fin_b0 = (const float*)d_in[17];
    const float* fin_b1 = (const float*)d_in[19];
    float* out = (float*)d_out;

    __half *p_h02, *p_h1, *p_aug, *p_g1, *p_g2, *p_finin, *p_f1;
    __half *p_w1, *p_w2, *p_w3, *p_kw0, *p_kw1, *p_fw0, *p_fw1;
    cudaGetSymbolAddress((void**)&p_h02,   g_h02);
    cudaGetSymbolAddress((void**)&p_h1,    g_h1);
    cudaGetSymbolAddress((void**)&p_aug,   g_aug);
    cudaGetSymbolAddress((void**)&p_g1,    g_g1);
    cudaGetSymbolAddress((void**)&p_g2,    g_g2);
    cudaGetSymbolAddress((void**)&p_finin, g_finin);
    cudaGetSymbolAddress((void**)&p_f1,    g_f1);
    cudaGetSymbolAddress((void**)&p_w1,    g_w1);
    cudaGetSymbolAddress((void**)&p_w2,    g_w2);
    cudaGetSymbolAddress((void**)&p_w3,    g_w3);
    cudaGetSymbolAddress((void**)&p_kw0,   g_kw0);
    cudaGetSymbolAddress((void**)&p_kw1,   g_kw1);
    cudaGetSymbolAddress((void**)&p_fw0,   g_fw0);
    cudaGetSymbolAddress((void**)&p_fw1,   g_fw1);

    cudaFuncSetAttribute(k_hgemm<0,1>, cudaFuncAttributeMaxDynamicSharedMemorySize, SMEM_BASE);
    cudaFuncSetAttribute(k_hgemm<3,1>, cudaFuncAttributeMaxDynamicSharedMemorySize, SMEM_BASE);
    cudaFuncSetAttribute(k_hgemm<2,4>, cudaFuncAttributeMaxDynamicSharedMemorySize, SMEM_SEG);

    k_wprep<<<(PREP_TOT + 255)/256, 256>>>(
        (const float*)d_in[6], (const float*)d_in[8], (const float*)d_in[10],
        (const float*)d_in[12], (const float*)d_in[14],
        (const float*)d_in[16], (const float*)d_in[18], out);

    k_assign<<<dim3(Nn/256, Bb), 256>>>(x, node);
    k_meancenter<<<1, 512>>>(knnI);
    k_l0<<<PTOT/256, 256>>>(x, sn, pr_w0, pr_b0);

    // PointResNet (HMMA fp16, BK=64)
    k_hgemm<0,1><<<dim3(PTOT/128, 1), 256, SMEM_BASE>>>(p_w1, p_h02, pr_b1, p_h1, PTOT, 64);
    k_hgemm<0,1><<<dim3(PTOT/128, 2), 256, SMEM_BASE>>>(p_w2, p_h1,  pr_b2, p_h02 + (size_t)64*PTOT, PTOT, 128);
    k_hgemm<2,4><<<dim3(PTOT/512, 3), 256, SMEM_SEG>>>(p_w3, p_h02, pr_b3, nullptr, PTOT, 320);

    // KNN module over SOM nodes
    k_aug<<<(K_AUG*QTOT + 255)/256, 256>>>(knnI);
    k_hgemm<0,1><<<dim3(QTOT/128, 4), 256, SMEM_BASE>>>(p_kw0, p_aug, knn_b0, p_g1, QTOT, K_AUG);
    k_hgemm<0,1><<<dim3(QTOT/128, 4), 256, SMEM_BASE>>>(p_kw1, p_g1,  knn_b1, p_g2, QTOT, 512);

    // final PointNet; last GEMM max-pools directly into out
    k_finin<<<(K_FIN*RTOT + 255)/256, 256>>>();
    k_hgemm<0,1><<<dim3(RTOT/128, 6), 256, SMEM_BASE>>>(p_fw0, p_finin, fin_b0, p_f1, RTOT, K_FIN);
    k_hgemm<3,1><<<dim3(RTOT/128, 8), 256, SMEM_BASE>>>(p_fw1, p_f1,    fin_b1, out,  RTOT, 768);
}

// round 11
// speedup vs baseline: 1.0742x; 1.0299x over previous
#include <cuda_runtime.h>
#include <cuda_fp16.h>
#include <cstdint>

// ---------------- problem dims --------------------------------------------
#define Bb   8
#define Nn   8192
#define Mm   64
#define KQ   3
#define KN   (KQ*Nn)        // 24576
#define PTOT (Bb*KN)        // 196608
#define SOMK 9
#define QTOT (Bb*Mm*SOMK)   // 4608
#define RTOT (Bb*Mm)        // 512
#define EPSF 1e-5f
#define K_AUG 448           // 387 padded to mult of 64
#define K_FIN 576           // 515 padded to mult of 64

// ---------------- scratch (device globals; no allocation) -----------------
__device__ __half g_h02[(size_t)320*PTOT];   // rows 0..63 = h0, 64..319 = h2
__device__ __half g_h1[(size_t)128*PTOT];
__device__ int    g_seg[PTOT];
__device__ float  g_cnt[Bb*Mm];
__device__ float  g_sum[Bb*3*Mm];
__device__ float  g_cmean[Bb*3*Mm];
__device__ float  g_center[Bb*3*Mm];
__device__ float  g_nodeMax[RTOT*384];
__device__ float  g_first0[Bb*384];
__device__ __half g_aug[(size_t)K_AUG*QTOT];
__device__ __half g_g1[(size_t)512*QTOT];
__device__ __half g_g2[(size_t)512*QTOT];
__device__ __half g_finin[(size_t)K_FIN*RTOT];
__device__ __half g_f1[(size_t)768*RTOT];
__device__ __half g_w1[128*64];
__device__ __half g_w2[256*128];
__device__ __half g_w3[384*320];
__device__ __half g_kw0[512*K_AUG];
__device__ __half g_kw1[512*512];
__device__ __half g_fw0[768*K_FIN];
__device__ __half g_fw1[1024*768];

// ---------------- PTX helpers ---------------------------------------------
__device__ __forceinline__ uint32_t smem_u32(const void* p) {
    uint32_t a;
    asm("{ .reg .u64 t; cvta.to.shared.u64 t, %1; cvt.u32.u64 %0, t; }" : "=r"(a) : "l"(p));
    return a;
}
#define CPA16(dst, src) \
    asm volatile("cp.async.cg.shared.global [%0], [%1], 16;" :: "r"(dst), "l"(src))
#define CPA_COMMIT() asm volatile("cp.async.commit_group;" ::: "memory")
#define CPA_WAIT(n)  asm volatile("cp.async.wait_group %0;" :: "n"(n) : "memory")

#define LDSM4(r0,r1,r2,r3,addr) \
    asm volatile("ldmatrix.sync.aligned.m8n8.x4.shared.b16 {%0,%1,%2,%3}, [%4];" \
        : "=r"(r0), "=r"(r1), "=r"(r2), "=r"(r3) : "r"(addr))
#define LDSM4T(r0,r1,r2,r3,addr) \
    asm volatile("ldmatrix.sync.aligned.m8n8.x4.trans.shared.b16 {%0,%1,%2,%3}, [%4];" \
        : "=r"(r0), "=r"(r1), "=r"(r2), "=r"(r3) : "r"(addr))

__device__ __forceinline__ void mma16816(float c[4], uint32_t a0, uint32_t a1,
                                         uint32_t a2, uint32_t a3,
                                         uint32_t b0, uint32_t b1) {
    asm volatile(
        "mma.sync.aligned.m16n8k16.row.col.f32.f16.f16.f32 "
        "{%0,%1,%2,%3}, {%4,%5,%6,%7}, {%8,%9}, {%0,%1,%2,%3};"
        : "+f"(c[0]), "+f"(c[1]), "+f"(c[2]), "+f"(c[3])
        : "r"(a0), "r"(a1), "r"(a2), "r"(a3), "r"(b0), "r"(b1));
}

#define APITCH 72                 // halves per A smem row (144 B)
#define A_STG (128*APITCH*2)      // 18432 B per 128-row x 64-k A tile
#define B_STG (64*128*2)          // 16384 B per 64-k x 128-n B tile
#define SMEM_BASE (2*A_STG + 2*B_STG)          // 69632
#define SMEM_SEG  (SMEM_BASE + 64*128*4)       // + 32768 = 102400

// ---------------- weight prep + zero (merged, also zeroes out) -------------
#define WTOT (128*64 + 256*128 + 384*320 + 512*K_AUG + 512*512 + 768*K_FIN + 1024*768)
#define PREP_TOT (WTOT + RTOT*384 + Bb*Mm + Bb*3*Mm + Bb*1024)
__global__ void k_wprep(const float* __restrict__ w1, const float* __restrict__ w2,
                        const float* __restrict__ w3, const float* __restrict__ kw0,
                        const float* __restrict__ kw1, const float* __restrict__ fw0,
                        const float* __restrict__ fw1, float* __restrict__ out) {
    int i = blockIdx.x*blockDim.x + threadIdx.x;
    if (i < 128*64)  { g_w1[i] = __float2half_rn(w1[i]); return; }  i -= 128*64;
    if (i < 256*128) { g_w2[i] = __float2half_rn(w2[i]); return; }  i -= 256*128;
    if (i < 384*320) { g_w3[i] = __float2half_rn(w3[i]); return; }  i -= 384*320;
    if (i < 512*K_AUG) { int r = i/K_AUG, c = i%K_AUG;
        g_kw0[i] = (c < 387) ? __float2half_rn(kw0[r*387 + c]) : __half(0.f); return; }
    i -= 512*K_AUG;
    if (i < 512*512) { g_kw1[i] = __float2half_rn(kw1[i]); return; }  i -= 512*512;
    if (i < 768*K_FIN) { int r = i/K_FIN, c = i%K_FIN;
        g_fw0[i] = (c < 515) ? __float2half_rn(fw0[r*515 + c]) : __half(0.f); return; }
    i -= 768*K_FIN;
    if (i < 1024*768) { g_fw1[i] = __float2half_rn(fw1[i]); return; }  i -= 1024*768;
    if (i < RTOT*384) { g_nodeMax[i] = 0.f; return; }  i -= RTOT*384;
    if (i < Bb*Mm)    { g_cnt[i] = 0.f; return; }      i -= Bb*Mm;
    if (i < Bb*3*Mm)  { g_sum[i] = 0.f; return; }      i -= Bb*3*Mm;
    if (i < Bb*1024)  out[i] = 0.f;
}

// ---------------- step 1: top-3 assignment + seg sums ----------------------
__global__ void k_assign(const float* __restrict__ x, const float* __restrict__ node) {
    int b  = blockIdx.y;
    int n  = blockIdx.x*blockDim.x + threadIdx.x;
    int tid = threadIdx.x;
    __shared__ float snode[3][Mm];
    __shared__ float scnt[Mm];
    __shared__ float ssum[3][Mm];
    if (tid < 3*Mm) { int c = tid/Mm, m = tid%Mm; snode[c][m] = node[(b*3+c)*Mm+m]; }
    if (tid < Mm)   scnt[tid] = 0.f;
    if (tid < 3*Mm) ((float*)ssum)[tid] = 0.f;
    __syncthreads();

    float x0 = x[(b*3+0)*Nn+n], x1 = x[(b*3+1)*Nn+n], x2 = x[(b*3+2)*Nn+n];
    float d0 = 1e30f, d1 = 1e30f, d2 = 1e30f;
    int   i0 = 0, i1 = 0, i2 = 0;
    #pragma unroll 8
    for (int m = 0; m < Mm; m++) {
        float dx = x0 - snode[0][m], dy = x1 - snode[1][m], dz = x2 - snode[2][m];
        float d = dx*dx + dy*dy + dz*dz;
        if (d < d2) {
            if (d < d1) {
                if (d < d0) { d2=d1; i2=i1; d1=d0; i1=i0; d0=d; i0=m; }
                else        { d2=d1; i2=i1; d1=d;  i1=m; }
            } else          { d2=d;  i2=m; }
        }
    }
    g_seg[b*KN + 0*Nn + n] = b*Mm + i0;
    g_seg[b*KN + 1*Nn + n] = b*Mm + i1;
    g_seg[b*KN + 2*Nn + n] = b*Mm + i2;

    atomicAdd(&scnt[i0], 1.f); atomicAdd(&scnt[i1], 1.f); atomicAdd(&scnt[i2], 1.f);
    atomicAdd(&ssum[0][i0], x0); atomicAdd(&ssum[1][i0], x1); atomicAdd(&ssum[2][i0], x2);
    atomicAdd(&ssum[0][i1], x0); atomicAdd(&ssum[1][i1], x1); atomicAdd(&ssum[2][i1], x2);
    atomicAdd(&ssum[0][i2], x0); atomicAdd(&ssum[1][i2], x1); atomicAdd(&ssum[2][i2], x2);
    __syncthreads();
    if (tid < Mm)   atomicAdd(&g_cnt[b*Mm+tid], scnt[tid]);
    if (tid < 3*Mm) { int c = tid/Mm, m = tid%Mm; atomicAdd(&g_sum[(b*3+c)*Mm+m], ssum[c][m]); }
}

// ---------------- mean + KNN center (single block) --------------------------
__global__ void k_meancenter(const int* __restrict__ I) {
    int tid = threadIdx.x;
    for (int i = tid; i < Bb*3*Mm; i += blockDim.x) {
        int m = i % Mm; int b = (i/Mm)/3;
        g_cmean[i] = g_sum[i] / (g_cnt[b*Mm+m] + EPSF);
    }
    __syncthreads();
    for (int i = tid; i < Bb*3*Mm; i += blockDim.x) {
        int m = i % Mm; int bc = i / Mm; int b = bc/3; int c = bc%3;
        float s = 0.f;
        #pragma unroll
        for (int kk = 0; kk < SOMK; kk++) {
            int im = I[(b*Mm+m)*SOMK + kk];
            s += g_cmean[(b*3+c)*Mm + im];
        }
        g_center[i] = s * (1.0f/SOMK);
    }
}

// ---------------- fused layer-0: 2 points/thread, half2 stores -------------
__global__ void k_l0(const float* __restrict__ x, const float* __restrict__ sn,
                     const float* __restrict__ w0, const float* __restrict__ b0) {
    __shared__ float sw[64*6];
    __shared__ float sb[64];
    int tid = threadIdx.x;
    for (int i = tid; i < 64*6; i += blockDim.x) sw[i] = w0[i];
    if (tid < 64) sb[tid] = b0[tid];
    __syncthreads();
    int p = (blockIdx.x*blockDim.x + tid) * 2;          // two consecutive points
    int n = p % Nn; int b = p / KN;                     // both points same b (Nn even)
    int nm0 = g_seg[p] % Mm, nm1 = g_seg[p+1] % Mm;
    float inA[6], inB[6];
    #pragma unroll
    for (int c = 0; c < 3; c++) {
        float2 xv = *(const float2*)&x[(b*3+c)*Nn+n];
        float2 sv = *(const float2*)&sn[(b*3+c)*Nn+n];
        inA[c]   = xv.x - g_cmean[(b*3+c)*Mm+nm0];
        inB[c]   = xv.y - g_cmean[(b*3+c)*Mm+nm1];
        inA[3+c] = sv.x;
        inB[3+c] = sv.y;
    }
    #pragma unroll
    for (int o = 0; o < 64; o++) {
        float a0 = sb[o], a1 = sb[o];
        #pragma unroll
        for (int c = 0; c < 6; c++) { a0 += sw[o*6+c]*inA[c]; a1 += sw[o*6+c]*inB[c]; }
        *(__half2*)&g_h02[(size_t)o*PTOT + p] =
            __floats2half2_rn(fmaxf(a0, 0.f), fmaxf(a1, 0.f));
    }
}

// ---------------- fp16 HMMA GEMM, BK=64 ------------------------------------
// Grid: x = row-block (M/128), y = col window. Row-blocks for the same col
// window are adjacent in dispatch order -> shared B tiles hit L2.
// OUT=0: fp16 C; OUT=2: smem segment-max + flush; OUT=3: atomicMax into out.
template<int OUT, int NX>
__global__ __launch_bounds__(256, 2)
void k_hgemm(const __half* __restrict__ A, const __half* __restrict__ Bm,
             const float* __restrict__ bias, void* __restrict__ C,
             int Nd, int Kd) {
    extern __shared__ __align__(1024) char dsm[];
    const uint32_t base = smem_u32(dsm);
    const uint32_t sA[2] = { base,            base + A_STG };
    const uint32_t sB[2] = { base + 2*A_STG,  base + 2*A_STG + B_STG };
    float* smax = (float*)(dsm + SMEM_BASE);

    const int tid  = threadIdx.x;
    const int lane = tid & 31, warp = tid >> 5;
    const int wm = warp & 3, wn = warp >> 2;
    const int rowBase = blockIdx.x * 128;            // SWAPPED: x = row-block
    const int colBase = blockIdx.y * (128*NX);       // SWAPPED: y = col window
    const int nT = Kd / 64;
    const __half* Arow = A + (size_t)rowBase*Kd;

    if (OUT == 2) {
        for (int i = tid; i < 64*128; i += 256) smax[i] = 0.f;
        __syncthreads();
    }

    for (int nx = 0; nx < NX; nx++) {
        const int cb = colBase + nx*128;
        const __half* Brow = Bm + cb;

        float acc[2][8][4];
        #pragma unroll
        for (int i = 0; i < 2; i++)
            #pragma unroll
            for (int j = 0; j < 8; j++)
                #pragma unroll
                for (int l = 0; l < 4; l++) acc[i][j][l] = 0.f;

        auto loadStage = [&](int t, int s) {
            #pragma unroll
            for (int i = 0; i < 4; i++) {
                int e = tid + i*256; int r = e >> 3, c = e & 7;
                CPA16(sA[s] + (uint32_t)(r*APITCH*2 + c*16),
                      (const char*)(Arow + (size_t)r*Kd + t*64 + c*8));
            }
            #pragma unroll
            for (int i = 0; i < 4; i++) {
                int e = tid + i*256; int k = e >> 4, c = e & 15;
                uint32_t off = (uint32_t)(k*256 + c*16);
                off ^= ((uint32_t)(k & 7)) << 4;
                CPA16(sB[s] + off, (const char*)(Brow + (size_t)(t*64 + k)*Nd + c*8));
            }
        };

        loadStage(0, 0); CPA_COMMIT();
        for (int t = 0; t < nT; t++) {
            if (t + 1 < nT) { loadStage(t + 1, (t + 1) & 1); CPA_COMMIT(); CPA_WAIT(1); }
            else            { CPA_WAIT(0); }
            __syncthreads();
            int buf = t & 1;
            #pragma unroll
            for (int ks = 0; ks < 4; ks++) {
                int kk = ks * 16;
                int mat = lane >> 3, r8 = lane & 7;
                uint32_t aF[2][4];
                #pragma unroll
                for (int mt = 0; mt < 2; mt++) {
                    int row = wm*32 + mt*16 + r8 + ((mat & 1) << 3);
                    int kof = kk + ((mat >> 1) << 3);
                    LDSM4(aF[mt][0], aF[mt][1], aF[mt][2], aF[mt][3],
                          sA[buf] + (uint32_t)(row*APITCH*2 + kof*2));
                }
                uint32_t bF[4][4];
                #pragma unroll
                for (int q = 0; q < 4; q++) {
                    int k = kk + r8 + ((mat & 1) << 3);
                    int n = wn*64 + q*16 + ((mat >> 1) << 3);
                    uint32_t off = (uint32_t)(k*256 + n*2);
                    off ^= ((uint32_t)(k & 7)) << 4;
                    LDSM4T(bF[q][0], bF[q][1], bF[q][2], bF[q][3], sB[buf] + off);
                }
                #pragma unroll
                for (int nt = 0; nt < 8; nt++) {
                    uint32_t b0 = bF[nt >> 1][(nt & 1)*2];
                    uint32_t b1 = bF[nt >> 1][(nt & 1)*2 + 1];
                    #pragma unroll
                    for (int mt = 0; mt < 2; mt++)
                        mma16816(acc[mt][nt], aF[mt][0], aF[mt][1], aF[mt][2], aF[mt][3], b0, b1);
                }
            }
            __syncthreads();
        }

        #pragma unroll
        for (int mt = 0; mt < 2; mt++) {
            int lr0 = wm*32 + mt*16 + (lane >> 2);
            int r0 = rowBase + lr0;
            float bv0 = bias[r0], bv1 = bias[r0 + 8];
            #pragma unroll
            for (int nt = 0; nt < 8; nt++) {
                int n0 = cb + wn*64 + nt*8 + 2*(lane & 3);
                float v00 = fmaxf(acc[mt][nt][0] + bv0, 0.f);
                float v01 = fmaxf(acc[mt][nt][1] + bv0, 0.f);
                float v10 = fmaxf(acc[mt][nt][2] + bv1, 0.f);
                float v11 = fmaxf(acc[mt][nt][3] + bv1, 0.f);
                if (OUT == 0) {
                    __half* Ch = (__half*)C;
                    *(__half2*)&Ch[(size_t)r0*Nd + n0]       = __floats2half2_rn(v00, v01);
                    *(__half2*)&Ch[(size_t)(r0 + 8)*Nd + n0] = __floats2half2_rn(v10, v11);
                } else if (OUT == 3) {
                    float* Of = (float*)C;
                    atomicMax((int*)&Of[(n0 >> 6)*1024 + r0],         __float_as_int(v00));
                    atomicMax((int*)&Of[((n0+1) >> 6)*1024 + r0],     __float_as_int(v01));
                    atomicMax((int*)&Of[(n0 >> 6)*1024 + r0 + 8],     __float_as_int(v10));
                    atomicMax((int*)&Of[((n0+1) >> 6)*1024 + r0 + 8], __float_as_int(v11));
                } else {
                    int s0 = g_seg[n0] & 63, s1 = g_seg[n0 + 1] & 63;
                    atomicMax((int*)&smax[s0*128 + lr0],     __float_as_int(v00));
                    atomicMax((int*)&smax[s1*128 + lr0],     __float_as_int(v01));
                    atomicMax((int*)&smax[s0*128 + lr0 + 8], __float_as_int(v10));
                    atomicMax((int*)&smax[s1*128 + lr0 + 8], __float_as_int(v11));
                    if ((n0 % KN) == 0) {
                        g_first0[(n0/KN)*384 + r0]     = v00;
                        g_first0[(n0/KN)*384 + r0 + 8] = v10;
                    }
                }
            }
        }
        if (OUT == 2) __syncthreads();
    }

    if (OUT == 2) {
        int bIdx = colBase / KN;
        for (int i = tid; i < 64*128; i += 256) {
            float v = smax[i];
            if (v > 0.f) {
                int node = i >> 7, lr = i & 127;
                atomicMax((int*)&g_nodeMax[(size_t)(bIdx*Mm + node)*384 + rowBase + lr],
                          __float_as_int(v));
            }
        }
    }
}

// ---------------- KNN module prep ------------------------------------------
__global__ void k_aug(const int* __restrict__ I) {
    int t = blockIdx.x*blockDim.x + threadIdx.x;
    if (t >= K_AUG*QTOT) return;
    int q = t % QTOT, c = t / QTOT;
    float v = 0.f;
    if (c < 387) {
        int kk = q % SOMK; int bm = q / SOMK; int b = bm / Mm; int m = bm % Mm;
        int im = I[bm*SOMK + kk];
        if (c < 3)
            v = g_cmean[(b*3+c)*Mm + im] - g_center[(b*3+c)*Mm + m];
        else
            v = (g_cnt[b*Mm+im] > 0.f) ? g_nodeMax[(size_t)(b*Mm+im)*384 + (c-3)]
                                       : g_first0[b*384 + (c-3)];
    }
    g_aug[t] = __float2half_rn(v);
}

__global__ void k_finin() {
    int t = blockIdx.x*blockDim.x + threadIdx.x;
    if (t >= K_FIN*RTOT) return;
    int r = t % RTOT, c = t / RTOT;
    float v = 0.f;
    if (c < 3) {
        int b = r / Mm, m = r % Mm;
        v = g_center[(b*3+c)*Mm + m];
    } else if (c < 515) {
        float mx = -1e30f;
        size_t base = (size_t)(c-3)*QTOT + (size_t)r*SOMK;
        #pragma unroll
        for (int kk = 0; kk < SOMK; kk++) mx = fmaxf(mx, __half2float(g_g2[base+kk]));
        v = mx;
    }
    g_finin[t] = __float2half_rn(v);
}

// ---------------- launch ----------------------------------------------------
extern "C" void kernel_launch(void* const* d_in, const int* in_sizes, int n_in,
                              void* d_out, int out_size) {
    const float* x      = (const float*)d_in[0];
    const float* sn     = (const float*)d_in[1];
    const float* node   = (const float*)d_in[2];
    const int*   knnI   = (const int*)  d_in[3];
    const float* pr_w0  = (const float*)d_in[4];
    const float* pr_b0  = (const float*)d_in[5];
    const float* pr_b1  = (const float*)d_in[7];
    const float* pr_b2  = (const float*)d_in[9];
    const float* pr_b3  = (const float*)d_in[11];
    const float* knn_b0 = (const float*)d_in[13];
    const float* knn_b1 = (const float*)d_in[15];
    const float* fin_b0 = (const float*)d_in[17];
    const float* fin_b1 = (const float*)d_in[19];
    float* out = (float*)d_out;

    __half *p_h02, *p_h1, *p_aug, *p_g1, *p_g2, *p_finin, *p_f1;
    __half *p_w1, *p_w2, *p_w3, *p_kw0, *p_kw1, *p_fw0, *p_fw1;
    cudaGetSymbolAddress((void**)&p_h02,   g_h02);
    cudaGetSymbolAddress((void**)&p_h1,    g_h1);
    cudaGetSymbolAddress((void**)&p_aug,   g_aug);
    cudaGetSymbolAddress((void**)&p_g1,    g_g1);
    cudaGetSymbolAddress((void**)&p_g2,    g_g2);
    cudaGetSymbolAddress((void**)&p_finin, g_finin);
    cudaGetSymbolAddress((void**)&p_f1,    g_f1);
    cudaGetSymbolAddress((void**)&p_w1,    g_w1);
    cudaGetSymbolAddress((void**)&p_w2,    g_w2);
    cudaGetSymbolAddress((void**)&p_w3,    g_w3);
    cudaGetSymbolAddress((void**)&p_kw0,   g_kw0);
    cudaGetSymbolAddress((void**)&p_kw1,   g_kw1);
    cudaGetSymbolAddress((void**)&p_fw0,   g_fw0);
    cudaGetSymbolAddress((void**)&p_fw1,   g_fw1);

    cudaFuncSetAttribute(k_hgemm<0,1>, cudaFuncAttributeMaxDynamicSharedMemorySize, SMEM_BASE);
    cudaFuncSetAttribute(k_hgemm<3,1>, cudaFuncAttributeMaxDynamicSharedMemorySize, SMEM_BASE);
    cudaFuncSetAttribute(k_hgemm<2,4>, cudaFuncAttributeMaxDynamicSharedMemorySize, SMEM_SEG);

    k_wprep<<<(PREP_TOT + 255)/256, 256>>>(
        (const float*)d_in[6], (const float*)d_in[8], (const float*)d_in[10],
        (const float*)d_in[12], (const float*)d_in[14],
        (const float*)d_in[16], (const float*)d_in[18], out);

    k_assign<<<dim3(Nn/256, Bb), 256>>>(x, node);
    k_meancenter<<<1, 512>>>(knnI);
    k_l0<<<PTOT/512, 256>>>(x, sn, pr_w0, pr_b0);

    // PointResNet (HMMA fp16, BK=64) — grid: (rowBlocks, colWindows)
    k_hgemm<0,1><<<dim3(1, PTOT/128), 256, SMEM_BASE>>>(p_w1, p_h02, pr_b1, p_h1, PTOT, 64);
    k_hgemm<0,1><<<dim3(2, PTOT/128), 256, SMEM_BASE>>>(p_w2, p_h1,  pr_b2, p_h02 + (size_t)64*PTOT, PTOT, 128);
    k_hgemm<2,4><<<dim3(3, PTOT/512), 256, SMEM_SEG>>>(p_w3, p_h02, pr_b3, nullptr, PTOT, 320);

    // KNN module over SOM nodes
    k_aug<<<(K_AUG*QTOT + 255)/256, 256>>>(knnI);
    k_hgemm<0,1><<<dim3(4, QTOT/128), 256, SMEM_BASE>>>(p_kw0, p_aug, knn_b0, p_g1, QTOT, K_AUG);
    k_hgemm<0,1><<<dim3(4, QTOT/128), 256, SMEM_BASE>>>(p_kw1, p_g1,  knn_b1, p_g2, QTOT, 512);

    // final PointNet; last GEMM max-pools directly into out
    k_finin<<<(K_FIN*RTOT + 255)/256, 256>>>();
    k_hgemm<0,1><<<dim3(6, RTOT/128), 256, SMEM_BASE>>>(p_fw0, p_finin, fin_b0, p_f1, RTOT, K_FIN);
    k_hgemm<3,1><<<dim3(8, RTOT/128), 256, SMEM_BASE>>>(p_fw1, p_f1,    fin_b1, out,  RTOT, 768);
}

// round 12
// speedup vs baseline: 1.1064x; 1.0299x over previous
#include <cuda_runtime.h>
#include <cuda_fp16.h>
#include <cstdint>

// ---------------- problem dims --------------------------------------------
#define Bb   8
#define Nn   8192
#define Mm   64
#define KQ   3
#define KN   (KQ*Nn)        // 24576
#define PTOT (Bb*KN)        // 196608
#define SOMK 9
#define QTOT (Bb*Mm*SOMK)   // 4608
#define RTOT (Bb*Mm)        // 512
#define EPSF 1e-5f
#define K_AUG 448
#define K_FIN 576

// ---------------- scratch (device globals; no allocation) -----------------
__device__ __half g_h02[(size_t)320*PTOT];
__device__ __half g_h1[(size_t)128*PTOT];
__device__ int    g_seg[PTOT];
__device__ float  g_cnt[Bb*Mm];
__device__ float  g_sum[Bb*3*Mm];
__device__ float  g_cmean[Bb*3*Mm];
__device__ float  g_center[Bb*3*Mm];
__device__ float  g_nodeMax[RTOT*384];
__device__ float  g_first0[Bb*384];
__device__ __half g_aug[(size_t)K_AUG*QTOT];
__device__ __half g_g1[(size_t)512*QTOT];
__device__ __half g_g2[(size_t)512*QTOT];
__device__ __half g_finin[(size_t)K_FIN*RTOT];
__device__ __half g_f1[(size_t)768*RTOT];
__device__ __half g_w1[128*64];
__device__ __half g_w2[256*128];
__device__ __half g_w3[384*320];
__device__ __half g_kw0[512*K_AUG];
__device__ __half g_kw1[512*512];
__device__ __half g_fw0[768*K_FIN];
__device__ __half g_fw1[1024*768];

// ---------------- PTX helpers ---------------------------------------------
__device__ __forceinline__ uint32_t smem_u32(const void* p) {
    uint32_t a;
    asm("{ .reg .u64 t; cvta.to.shared.u64 t, %1; cvt.u32.u64 %0, t; }" : "=r"(a) : "l"(p));
    return a;
}
#define CPA16(dst, src) \
    asm volatile("cp.async.cg.shared.global [%0], [%1], 16;" :: "r"(dst), "l"(src))
#define CPA_COMMIT() asm volatile("cp.async.commit_group;" ::: "memory")
#define CPA_WAIT(n)  asm volatile("cp.async.wait_group %0;" :: "n"(n) : "memory")

#define LDSM4(r0,r1,r2,r3,addr) \
    asm volatile("ldmatrix.sync.aligned.m8n8.x4.shared.b16 {%0,%1,%2,%3}, [%4];" \
        : "=r"(r0), "=r"(r1), "=r"(r2), "=r"(r3) : "r"(addr))
#define LDSM4T(r0,r1,r2,r3,addr) \
    asm volatile("ldmatrix.sync.aligned.m8n8.x4.trans.shared.b16 {%0,%1,%2,%3}, [%4];" \
        : "=r"(r0), "=r"(r1), "=r"(r2), "=r"(r3) : "r"(addr))

__device__ __forceinline__ void mma16816(float c[4], uint32_t a0, uint32_t a1,
                                         uint32_t a2, uint32_t a3,
                                         uint32_t b0, uint32_t b1) {
    asm volatile(
        "mma.sync.aligned.m16n8k16.row.col.f32.f16.f16.f32 "
        "{%0,%1,%2,%3}, {%4,%5,%6,%7}, {%8,%9}, {%0,%1,%2,%3};"
        : "+f"(c[0]), "+f"(c[1]), "+f"(c[2]), "+f"(c[3])
        : "r"(a0), "r"(a1), "r"(a2), "r"(a3), "r"(b0), "r"(b1));
}

#define APITCH 72
#define B_STG (64*128*2)          // 16384 B per 64-k x 128-n B tile
// MW=4: A stage 18432 B -> SMEM 69632 (+32768 segmax = 102400)
// MW=2: A stage  9216 B -> SMEM 51200
#define SMEM_MW(MW)  (2*((MW)*32*APITCH*2) + 2*B_STG)
#define SMEM_SEG     (SMEM_MW(4) + 64*128*4)

// ---------------- weight prep + zero (merged) -------------------------------
#define WTOT (128*64 + 256*128 + 384*320 + 512*K_AUG + 512*512 + 768*K_FIN + 1024*768)
#define PREP_TOT (WTOT + RTOT*384 + Bb*Mm + Bb*3*Mm + Bb*1024)
__global__ void k_wprep(const float* __restrict__ w1, const float* __restrict__ w2,
                        const float* __restrict__ w3, const float* __restrict__ kw0,
                        const float* __restrict__ kw1, const float* __restrict__ fw0,
                        const float* __restrict__ fw1, float* __restrict__ out) {
    int i = blockIdx.x*blockDim.x + threadIdx.x;
    if (i < 128*64)  { g_w1[i] = __float2half_rn(w1[i]); return; }  i -= 128*64;
    if (i < 256*128) { g_w2[i] = __float2half_rn(w2[i]); return; }  i -= 256*128;
    if (i < 384*320) { g_w3[i] = __float2half_rn(w3[i]); return; }  i -= 384*320;
    if (i < 512*K_AUG) { int r = i/K_AUG, c = i%K_AUG;
        g_kw0[i] = (c < 387) ? __float2half_rn(kw0[r*387 + c]) : __half(0.f); return; }
    i -= 512*K_AUG;
    if (i < 512*512) { g_kw1[i] = __float2half_rn(kw1[i]); return; }  i -= 512*512;
    if (i < 768*K_FIN) { int r = i/K_FIN, c = i%K_FIN;
        g_fw0[i] = (c < 515) ? __float2half_rn(fw0[r*515 + c]) : __half(0.f); return; }
    i -= 768*K_FIN;
    if (i < 1024*768) { g_fw1[i] = __float2half_rn(fw1[i]); return; }  i -= 1024*768;
    if (i < RTOT*384) { g_nodeMax[i] = 0.f; return; }  i -= RTOT*384;
    if (i < Bb*Mm)    { g_cnt[i] = 0.f; return; }      i -= Bb*Mm;
    if (i < Bb*3*Mm)  { g_sum[i] = 0.f; return; }      i -= Bb*3*Mm;
    if (i < Bb*1024)  out[i] = 0.f;
}

// ---------------- step 1: top-3 assignment + seg sums ----------------------
__global__ void k_assign(const float* __restrict__ x, const float* __restrict__ node) {
    int b  = blockIdx.y;
    int n  = blockIdx.x*blockDim.x + threadIdx.x;
    int tid = threadIdx.x;
    __shared__ float snode[3][Mm];
    __shared__ float scnt[Mm];
    __shared__ float ssum[3][Mm];
    if (tid < 3*Mm) { int c = tid/Mm, m = tid%Mm; snode[c][m] = node[(b*3+c)*Mm+m]; }
    if (tid < Mm)   scnt[tid] = 0.f;
    if (tid < 3*Mm) ((float*)ssum)[tid] = 0.f;
    __syncthreads();

    float x0 = x[(b*3+0)*Nn+n], x1 = x[(b*3+1)*Nn+n], x2 = x[(b*3+2)*Nn+n];
    float d0 = 1e30f, d1 = 1e30f, d2 = 1e30f;
    int   i0 = 0, i1 = 0, i2 = 0;
    #pragma unroll 8
    for (int m = 0; m < Mm; m++) {
        float dx = x0 - snode[0][m], dy = x1 - snode[1][m], dz = x2 - snode[2][m];
        float d = dx*dx + dy*dy + dz*dz;
        if (d < d2) {
            if (d < d1) {
                if (d < d0) { d2=d1; i2=i1; d1=d0; i1=i0; d0=d; i0=m; }
                else        { d2=d1; i2=i1; d1=d;  i1=m; }
            } else          { d2=d;  i2=m; }
        }
    }
    g_seg[b*KN + 0*Nn + n] = b*Mm + i0;
    g_seg[b*KN + 1*Nn + n] = b*Mm + i1;
    g_seg[b*KN + 2*Nn + n] = b*Mm + i2;

    atomicAdd(&scnt[i0], 1.f); atomicAdd(&scnt[i1], 1.f); atomicAdd(&scnt[i2], 1.f);
    atomicAdd(&ssum[0][i0], x0); atomicAdd(&ssum[1][i0], x1); atomicAdd(&ssum[2][i0], x2);
    atomicAdd(&ssum[0][i1], x0); atomicAdd(&ssum[1][i1], x1); atomicAdd(&ssum[2][i1], x2);
    atomicAdd(&ssum[0][i2], x0); atomicAdd(&ssum[1][i2], x1); atomicAdd(&ssum[2][i2], x2);
    __syncthreads();
    if (tid < Mm)   atomicAdd(&g_cnt[b*Mm+tid], scnt[tid]);
    if (tid < 3*Mm) { int c = tid/Mm, m = tid%Mm; atomicAdd(&g_sum[(b*3+c)*Mm+m], ssum[c][m]); }
}

// ---------------- mean + KNN center (single block) --------------------------
__global__ void k_meancenter(const int* __restrict__ I) {
    int tid = threadIdx.x;
    for (int i = tid; i < Bb*3*Mm; i += blockDim.x) {
        int m = i % Mm; int b = (i/Mm)/3;
        g_cmean[i] = g_sum[i] / (g_cnt[b*Mm+m] + EPSF);
    }
    __syncthreads();
    for (int i = tid; i < Bb*3*Mm; i += blockDim.x) {
        int m = i % Mm; int bc = i / Mm; int b = bc/3; int c = bc%3;
        float s = 0.f;
        #pragma unroll
        for (int kk = 0; kk < SOMK; kk++) {
            int im = I[(b*Mm+m)*SOMK + kk];
            s += g_cmean[(b*3+c)*Mm + im];
        }
        g_center[i] = s * (1.0f/SOMK);
    }
}

// ---------------- fused layer-0: 2 points/thread, half2 stores -------------
__global__ void k_l0(const float* __restrict__ x, const float* __restrict__ sn,
                     const float* __restrict__ w0, const float* __restrict__ b0) {
    __shared__ float sw[64*6];
    __shared__ float sb[64];
    int tid = threadIdx.x;
    for (int i = tid; i < 64*6; i += blockDim.x) sw[i] = w0[i];
    if (tid < 64) sb[tid] = b0[tid];
    __syncthreads();
    int p = (blockIdx.x*blockDim.x + tid) * 2;
    int n = p % Nn; int b = p / KN;
    int nm0 = g_seg[p] % Mm, nm1 = g_seg[p+1] % Mm;
    float inA[6], inB[6];
    #pragma unroll
    for (int c = 0; c < 3; c++) {
        float2 xv = *(const float2*)&x[(b*3+c)*Nn+n];
        float2 sv = *(const float2*)&sn[(b*3+c)*Nn+n];
        inA[c]   = xv.x - g_cmean[(b*3+c)*Mm+nm0];
        inB[c]   = xv.y - g_cmean[(b*3+c)*Mm+nm1];
        inA[3+c] = sv.x;
        inB[3+c] = sv.y;
    }
    #pragma unroll
    for (int o = 0; o < 64; o++) {
        float a0 = sb[o], a1 = sb[o];
        #pragma unroll
        for (int c = 0; c < 6; c++) { a0 += sw[o*6+c]*inA[c]; a1 += sw[o*6+c]*inB[c]; }
        *(__half2*)&g_h02[(size_t)o*PTOT + p] =
            __floats2half2_rn(fmaxf(a0, 0.f), fmaxf(a1, 0.f));
    }
}

// ---------------- fp16 HMMA GEMM, BK=64, templated M-tile -------------------
// MW = warps along M (4 -> 128-row tile [current proven config], 2 -> 64-row).
// OUT=0: fp16 C; OUT=2: smem segment-max + flush (MW=4 only); OUT=3: atomicMax out.
template<int OUT, int NX, int MW>
__global__ __launch_bounds__(256, 2)
void k_hgemm(const __half* __restrict__ A, const __half* __restrict__ Bm,
             const float* __restrict__ bias, void* __restrict__ C,
             int Nd, int Kd) {
    constexpr int MROWS = MW*32;            // CTA M tile
    constexpr int NW    = 8/MW;             // warps along N
    constexpr int NPW   = 128/NW;           // cols per warp
    constexpr int NTC   = NPW/8;            // 8-col sub-tiles per warp
    constexpr int ASB   = MROWS*APITCH*2;   // A stage bytes

    extern __shared__ __align__(1024) char dsm[];
    const uint32_t base = smem_u32(dsm);
    const uint32_t sA[2] = { base,           base + ASB };
    const uint32_t sB[2] = { base + 2*ASB,   base + 2*ASB + B_STG };
    float* smax = (float*)(dsm + SMEM_MW(4));

    const int tid  = threadIdx.x;
    const int lane = tid & 31, warp = tid >> 5;
    const int wm = warp % MW, wn = warp / MW;
    const int rowBase = blockIdx.x * MROWS;
    const int colBase = blockIdx.y * (128*NX);
    const int nT = Kd / 64;
    const __half* Arow = A + (size_t)rowBase*Kd;

    if (OUT == 2) {
        for (int i = tid; i < 64*128; i += 256) smax[i] = 0.f;
        __syncthreads();
    }

    for (int nx = 0; nx < NX; nx++) {
        const int cb = colBase + nx*128;
        const __half* Brow = Bm + cb;

        float acc[2][NTC][4];
        #pragma unroll
        for (int i = 0; i < 2; i++)
            #pragma unroll
            for (int j = 0; j < NTC; j++)
                #pragma unroll
                for (int l = 0; l < 4; l++) acc[i][j][l] = 0.f;

        auto loadStage = [&](int t, int s) {
            #pragma unroll
            for (int i = 0; i < MW; i++) {          // MROWS*8 chunks
                int e = tid + i*256; int r = e >> 3, c = e & 7;
                CPA16(sA[s] + (uint32_t)(r*APITCH*2 + c*16),
                      (const char*)(Arow + (size_t)r*Kd + t*64 + c*8));
            }
            #pragma unroll
            for (int i = 0; i < 4; i++) {
                int e = tid + i*256; int k = e >> 4, c = e & 15;
                uint32_t off = (uint32_t)(k*256 + c*16);
                off ^= ((uint32_t)(k & 7)) << 4;
                CPA16(sB[s] + off, (const char*)(Brow + (size_t)(t*64 + k)*Nd + c*8));
            }
        };

        loadStage(0, 0); CPA_COMMIT();
        for (int t = 0; t < nT; t++) {
            if (t + 1 < nT) { loadStage(t + 1, (t + 1) & 1); CPA_COMMIT(); CPA_WAIT(1); }
            else            { CPA_WAIT(0); }
            __syncthreads();
            int buf = t & 1;
            #pragma unroll
            for (int ks = 0; ks < 4; ks++) {
                int kk = ks * 16;
                int mat = lane >> 3, r8 = lane & 7;
                uint32_t aF[2][4];
                #pragma unroll
                for (int mt = 0; mt < 2; mt++) {
                    int row = wm*32 + mt*16 + r8 + ((mat & 1) << 3);
                    int kof = kk + ((mat >> 1) << 3);
                    LDSM4(aF[mt][0], aF[mt][1], aF[mt][2], aF[mt][3],
                          sA[buf] + (uint32_t)(row*APITCH*2 + kof*2));
                }
                uint32_t bF[MW][4];
                #pragma unroll
                for (int q = 0; q < MW; q++) {      // NPW/16 x4-loads
                    int k = kk + r8 + ((mat & 1) << 3);
                    int n = wn*NPW + q*16 + ((mat >> 1) << 3);
                    uint32_t off = (uint32_t)(k*256 + n*2);
                    off ^= ((uint32_t)(k & 7)) << 4;
                    LDSM4T(bF[q][0], bF[q][1], bF[q][2], bF[q][3], sB[buf] + off);
                }
                #pragma unroll
                for (int nt = 0; nt < NTC; nt++) {
                    uint32_t b0 = bF[nt >> 1][(nt & 1)*2];
                    uint32_t b1 = bF[nt >> 1][(nt & 1)*2 + 1];
                    #pragma unroll
                    for (int mt = 0; mt < 2; mt++)
                        mma16816(acc[mt][nt], aF[mt][0], aF[mt][1], aF[mt][2], aF[mt][3], b0, b1);
                }
            }
            __syncthreads();
        }

        #pragma unroll
        for (int mt = 0; mt < 2; mt++) {
            int lr0 = wm*32 + mt*16 + (lane >> 2);
            int r0 = rowBase + lr0;
            float bv0 = bias[r0], bv1 = bias[r0 + 8];
            #pragma unroll
            for (int nt = 0; nt < NTC; nt++) {
                int n0 = cb + wn*NPW + nt*8 + 2*(lane & 3);
                float v00 = fmaxf(acc[mt][nt][0] + bv0, 0.f);
                float v01 = fmaxf(acc[mt][nt][1] + bv0, 0.f);
                float v10 = fmaxf(acc[mt][nt][2] + bv1, 0.f);
                float v11 = fmaxf(acc[mt][nt][3] + bv1, 0.f);
                if (OUT == 0) {
                    __half* Ch = (__half*)C;
                    *(__half2*)&Ch[(size_t)r0*Nd + n0]       = __floats2half2_rn(v00, v01);
                    *(__half2*)&Ch[(size_t)(r0 + 8)*Nd + n0] = __floats2half2_rn(v10, v11);
                } else if (OUT == 3) {
                    float* Of = (float*)C;
                    atomicMax((int*)&Of[(n0 >> 6)*1024 + r0],         __float_as_int(v00));
                    atomicMax((int*)&Of[((n0+1) >> 6)*1024 + r0],     __float_as_int(v01));
                    atomicMax((int*)&Of[(n0 >> 6)*1024 + r0 + 8],     __float_as_int(v10));
                    atomicMax((int*)&Of[((n0+1) >> 6)*1024 + r0 + 8], __float_as_int(v11));
                } else {
                    int s0 = g_seg[n0] & 63, s1 = g_seg[n0 + 1] & 63;
                    atomicMax((int*)&smax[s0*128 + lr0],     __float_as_int(v00));
                    atomicMax((int*)&smax[s1*128 + lr0],     __float_as_int(v01));
                    atomicMax((int*)&smax[s0*128 + lr0 + 8], __float_as_int(v10));
                    atomicMax((int*)&smax[s1*128 + lr0 + 8], __float_as_int(v11));
                    if ((n0 % KN) == 0) {
                        g_first0[(n0/KN)*384 + r0]     = v00;
                        g_first0[(n0/KN)*384 + r0 + 8] = v10;
                    }
                }
            }
        }
        if (OUT == 2) __syncthreads();
    }

    if (OUT == 2) {
        int bIdx = colBase / KN;
        for (int i = tid; i < 64*128; i += 256) {
            float v = smax[i];
            if (v > 0.f) {
                int node = i >> 7, lr = i & 127;
                atomicMax((int*)&g_nodeMax[(size_t)(bIdx*Mm + node)*384 + rowBase + lr],
                          __float_as_int(v));
            }
        }
    }
}

// ---------------- KNN module prep ------------------------------------------
__global__ void k_aug(const int* __restrict__ I) {
    int t = blockIdx.x*blockDim.x + threadIdx.x;
    if (t >= K_AUG*QTOT) return;
    int q = t % QTOT, c = t / QTOT;
    float v = 0.f;
    if (c < 387) {
        int kk = q % SOMK; int bm = q / SOMK; int b = bm / Mm; int m = bm % Mm;
        int im = I[bm*SOMK + kk];
        if (c < 3)
            v = g_cmean[(b*3+c)*Mm + im] - g_center[(b*3+c)*Mm + m];
        else
            v = (g_cnt[b*Mm+im] > 0.f) ? g_nodeMax[(size_t)(b*Mm+im)*384 + (c-3)]
                                       : g_first0[b*384 + (c-3)];
    }
    g_aug[t] = __float2half_rn(v);
}

__global__ void k_finin() {
    int t = blockIdx.x*blockDim.x + threadIdx.x;
    if (t >= K_FIN*RTOT) return;
    int r = t % RTOT, c = t / RTOT;
    float v = 0.f;
    if (c < 3) {
        int b = r / Mm, m = r % Mm;
        v = g_center[(b*3+c)*Mm + m];
    } else if (c < 515) {
        float mx = -1e30f;
        size_t base = (size_t)(c-3)*QTOT + (size_t)r*SOMK;
        #pragma unroll
        for (int kk = 0; kk < SOMK; kk++) mx = fmaxf(mx, __half2float(g_g2[base+kk]));
        v = mx;
    }
    g_finin[t] = __float2half_rn(v);
}

// ---------------- launch ----------------------------------------------------
extern "C" void kernel_launch(void* const* d_in, const int* in_sizes, int n_in,
                              void* d_out, int out_size) {
    const float* x      = (const float*)d_in[0];
    const float* sn     = (const float*)d_in[1];
    const float* node   = (const float*)d_in[2];
    const int*   knnI   = (const int*)  d_in[3];
    const float* pr_w0  = (const float*)d_in[4];
    const float* pr_b0  = (const float*)d_in[5];
    const float* pr_b1  = (const float*)d_in[7];
    const float* pr_b2  = (const float*)d_in[9];
    const float* pr_b3  = (const float*)d_in[11];
    const float* knn_b0 = (const float*)d_in[13];
    const float* knn_b1 = (const float*)d_in[15];
    const float* fin_b0 = (const float*)d_in[17];
    const float* fin_b1 = (const float*)d_in[19];
    float* out = (float*)d_out;

    __half *p_h02, *p_h1, *p_aug, *p_g1, *p_g2, *p_finin, *p_f1;
    __half *p_w1, *p_w2, *p_w3, *p_kw0, *p_kw1, *p_fw0, *p_fw1;
    cudaGetSymbolAddress((void**)&p_h02,   g_h02);
    cudaGetSymbolAddress((void**)&p_h1,    g_h1);
    cudaGetSymbolAddress((void**)&p_aug,   g_aug);
    cudaGetSymbolAddress((void**)&p_g1,    g_g1);
    cudaGetSymbolAddress((void**)&p_g2,    g_g2);
    cudaGetSymbolAddress((void**)&p_finin, g_finin);
    cudaGetSymbolAddress((void**)&p_f1,    g_f1);
    cudaGetSymbolAddress((void**)&p_w1,    g_w1);
    cudaGetSymbolAddress((void**)&p_w2,    g_w2);
    cudaGetSymbolAddress((void**)&p_w3,    g_w3);
    cudaGetSymbolAddress((void**)&p_kw0,   g_kw0);
    cudaGetSymbolAddress((void**)&p_kw1,   g_kw1);
    cudaGetSymbolAddress((void**)&p_fw0,   g_fw0);
    cudaGetSymbolAddress((void**)&p_fw1,   g_fw1);

    cudaFuncSetAttribute(k_hgemm<0,1,4>, cudaFuncAttributeMaxDynamicSharedMemorySize, SMEM_MW(4));
    cudaFuncSetAttribute(k_hgemm<0,1,2>, cudaFuncAttributeMaxDynamicSharedMemorySize, SMEM_MW(2));
    cudaFuncSetAttribute(k_hgemm<3,1,2>, cudaFuncAttributeMaxDynamicSharedMemorySize, SMEM_MW(2));
    cudaFuncSetAttribute(k_hgemm<2,4,4>, cudaFuncAttributeMaxDynamicSharedMemorySize, SMEM_SEG);

    k_wprep<<<(PREP_TOT + 255)/256, 256>>>(
        (const float*)d_in[6], (const float*)d_in[8], (const float*)d_in[10],
        (const float*)d_in[12], (const float*)d_in[14],
        (const float*)d_in[16], (const float*)d_in[18], out);

    k_assign<<<dim3(Nn/256, Bb), 256>>>(x, node);
    k_meancenter<<<1, 512>>>(knnI);
    k_l0<<<PTOT/512, 256>>>(x, sn, pr_w0, pr_b0);

    // PointResNet (HMMA fp16, BK=64, 128-row tiles)
    k_hgemm<0,1,4><<<dim3(1, PTOT/128), 256, SMEM_MW(4)>>>(p_w1, p_h02, pr_b1, p_h1, PTOT, 64);
    k_hgemm<0,1,4><<<dim3(2, PTOT/128), 256, SMEM_MW(4)>>>(p_w2, p_h1,  pr_b2, p_h02 + (size_t)64*PTOT, PTOT, 128);
    k_hgemm<2,4,4><<<dim3(3, PTOT/512), 256, SMEM_SEG>>>(p_w3, p_h02, pr_b3, nullptr, PTOT, 320);

    // KNN module over SOM nodes (64-row tiles -> 288 CTAs each)
    k_aug<<<(K_AUG*QTOT + 255)/256, 256>>>(knnI);
    k_hgemm<0,1,2><<<dim3(8, QTOT/128), 256, SMEM_MW(2)>>>(p_kw0, p_aug, knn_b0, p_g1, QTOT, K_AUG);
    k_hgemm<0,1,2><<<dim3(8, QTOT/128), 256, SMEM_MW(2)>>>(p_kw1, p_g1,  knn_b1, p_g2, QTOT, 512);

    // final PointNet (64-row tiles); last GEMM max-pools directly into out
    k_finin<<<(K_FIN*RTOT + 255)/256, 256>>>();
    k_hgemm<0,1,2><<<dim3(12, RTOT/128), 256, SMEM_MW(2)>>>(p_fw0, p_finin, fin_b0, p_f1, RTOT, K_FIN);
    k_hgemm<3,1,2><<<dim3(16, RTOT/128), 256, SMEM_MW(2)>>>(p_fw1, p_f1,    fin_b1, out,  RTOT, 768);
}

// round 13
// speedup vs baseline: 1.1085x; 1.0019x over previous
#include <cuda_runtime.h>
#include <cuda_fp16.h>
#include <cstdint>

// ---------------- problem dims --------------------------------------------
#define Bb   8
#define Nn   8192
#define Mm   64
#define KQ   3
#define KN   (KQ*Nn)        // 24576
#define PTOT (Bb*KN)        // 196608
#define SOMK 9
#define QTOT (Bb*Mm*SOMK)   // 4608
#define RTOT (Bb*Mm)        // 512
#define EPSF 1e-5f
#define K_AUG 448
#define K_FIN 576

// ---------------- scratch (device globals; no allocation) -----------------
__device__ __half g_h02[(size_t)320*PTOT];
__device__ __half g_h1[(size_t)128*PTOT];
__device__ int    g_seg[PTOT];
__device__ float  g_cnt[Bb*Mm];
__device__ float  g_sum[Bb*3*Mm];
__device__ float  g_cmean[Bb*3*Mm];
__device__ float  g_center[Bb*3*Mm];
__device__ float  g_nodeMax[RTOT*384];
__device__ float  g_first0[Bb*384];
__device__ __half g_aug[(size_t)K_AUG*QTOT];
__device__ __half g_g1[(size_t)512*QTOT];
__device__ __half g_g2[(size_t)512*QTOT];
__device__ __half g_finin[(size_t)K_FIN*RTOT];
__device__ __half g_f1[(size_t)768*RTOT];
__device__ __half g_w1[128*64];
__device__ __half g_w2[256*128];
__device__ __half g_w3[384*320];
__device__ __half g_kw0[512*K_AUG];
__device__ __half g_kw1[512*512];
__device__ __half g_fw0[768*K_FIN];
__device__ __half g_fw1[1024*768];

// ---------------- PTX helpers ---------------------------------------------
__device__ __forceinline__ uint32_t smem_u32(const void* p) {
    uint32_t a;
    asm("{ .reg .u64 t; cvta.to.shared.u64 t, %1; cvt.u32.u64 %0, t; }" : "=r"(a) : "l"(p));
    return a;
}
#define CPA16(dst, src) \
    asm volatile("cp.async.cg.shared.global [%0], [%1], 16;" :: "r"(dst), "l"(src))
#define CPA_COMMIT() asm volatile("cp.async.commit_group;" ::: "memory")
#define CPA_WAIT(n)  asm volatile("cp.async.wait_group %0;" :: "n"(n) : "memory")

#define LDSM4(r0,r1,r2,r3,addr) \
    asm volatile("ldmatrix.sync.aligned.m8n8.x4.shared.b16 {%0,%1,%2,%3}, [%4];" \
        : "=r"(r0), "=r"(r1), "=r"(r2), "=r"(r3) : "r"(addr))
#define LDSM4T(r0,r1,r2,r3,addr) \
    asm volatile("ldmatrix.sync.aligned.m8n8.x4.trans.shared.b16 {%0,%1,%2,%3}, [%4];" \
        : "=r"(r0), "=r"(r1), "=r"(r2), "=r"(r3) : "r"(addr))

__device__ __forceinline__ void mma16816(float c[4], uint32_t a0, uint32_t a1,
                                         uint32_t a2, uint32_t a3,
                                         uint32_t b0, uint32_t b1) {
    asm volatile(
        "mma.sync.aligned.m16n8k16.row.col.f32.f16.f16.f32 "
        "{%0,%1,%2,%3}, {%4,%5,%6,%7}, {%8,%9}, {%0,%1,%2,%3};"
        : "+f"(c[0]), "+f"(c[1]), "+f"(c[2]), "+f"(c[3])
        : "r"(a0), "r"(a1), "r"(a2), "r"(a3), "r"(b0), "r"(b1));
}

#define APITCH 72
#define B_STG (64*128*2)          // 16384 B per 64-k x 128-n B tile
#define SMEM_MW(MW)  (2*((MW)*32*APITCH*2) + 2*B_STG)
#define SMEM_SEG     (SMEM_MW(4) + 64*128*4)

// ---------------- weight prep + zero (merged) -------------------------------
#define WTOT (128*64 + 256*128 + 384*320 + 512*K_AUG + 512*512 + 768*K_FIN + 1024*768)
#define PREP_TOT (WTOT + RTOT*384 + Bb*Mm + Bb*3*Mm + Bb*1024)
__global__ void k_wprep(const float* __restrict__ w1, const float* __restrict__ w2,
                        const float* __restrict__ w3, const float* __restrict__ kw0,
                        const float* __restrict__ kw1, const float* __restrict__ fw0,
                        const float* __restrict__ fw1, float* __restrict__ out) {
    int i = blockIdx.x*blockDim.x + threadIdx.x;
    if (i < 128*64)  { g_w1[i] = __float2half_rn(w1[i]); return; }  i -= 128*64;
    if (i < 256*128) { g_w2[i] = __float2half_rn(w2[i]); return; }  i -= 256*128;
    if (i < 384*320) { g_w3[i] = __float2half_rn(w3[i]); return; }  i -= 384*320;
    if (i < 512*K_AUG) { int r = i/K_AUG, c = i%K_AUG;
        g_kw0[i] = (c < 387) ? __float2half_rn(kw0[r*387 + c]) : __half(0.f); return; }
    i -= 512*K_AUG;
    if (i < 512*512) { g_kw1[i] = __float2half_rn(kw1[i]); return; }  i -= 512*512;
    if (i < 768*K_FIN) { int r = i/K_FIN, c = i%K_FIN;
        g_fw0[i] = (c < 515) ? __float2half_rn(fw0[r*515 + c]) : __half(0.f); return; }
    i -= 768*K_FIN;
    if (i < 1024*768) { g_fw1[i] = __float2half_rn(fw1[i]); return; }  i -= 1024*768;
    if (i < RTOT*384) { g_nodeMax[i] = 0.f; return; }  i -= RTOT*384;
    if (i < Bb*Mm)    { g_cnt[i] = 0.f; return; }      i -= Bb*Mm;
    if (i < Bb*3*Mm)  { g_sum[i] = 0.f; return; }      i -= Bb*3*Mm;
    if (i < Bb*1024)  out[i] = 0.f;
}

// ---------------- step 1: top-3 assignment + seg sums ----------------------
__global__ void k_assign(const float* __restrict__ x, const float* __restrict__ node) {
    int b  = blockIdx.y;
    int n  = blockIdx.x*blockDim.x + threadIdx.x;
    int tid = threadIdx.x;
    __shared__ float snode[3][Mm];
    __shared__ float scnt[Mm];
    __shared__ float ssum[3][Mm];
    if (tid < 3*Mm) { int c = tid/Mm, m = tid%Mm; snode[c][m] = node[(b*3+c)*Mm+m]; }
    if (tid < Mm)   scnt[tid] = 0.f;
    if (tid < 3*Mm) ((float*)ssum)[tid] = 0.f;
    __syncthreads();

    float x0 = x[(b*3+0)*Nn+n], x1 = x[(b*3+1)*Nn+n], x2 = x[(b*3+2)*Nn+n];
    float d0 = 1e30f, d1 = 1e30f, d2 = 1e30f;
    int   i0 = 0, i1 = 0, i2 = 0;
    #pragma unroll 8
    for (int m = 0; m < Mm; m++) {
        float dx = x0 - snode[0][m], dy = x1 - snode[1][m], dz = x2 - snode[2][m];
        float d = dx*dx + dy*dy + dz*dz;
        if (d < d2) {
            if (d < d1) {
                if (d < d0) { d2=d1; i2=i1; d1=d0; i1=i0; d0=d; i0=m; }
                else        { d2=d1; i2=i1; d1=d;  i1=m; }
            } else          { d2=d;  i2=m; }
        }
    }
    g_seg[b*KN + 0*Nn + n] = b*Mm + i0;
    g_seg[b*KN + 1*Nn + n] = b*Mm + i1;
    g_seg[b*KN + 2*Nn + n] = b*Mm + i2;

    atomicAdd(&scnt[i0], 1.f); atomicAdd(&scnt[i1], 1.f); atomicAdd(&scnt[i2], 1.f);
    atomicAdd(&ssum[0][i0], x0); atomicAdd(&ssum[1][i0], x1); atomicAdd(&ssum[2][i0], x2);
    atomicAdd(&ssum[0][i1], x0); atomicAdd(&ssum[1][i1], x1); atomicAdd(&ssum[2][i1], x2);
    atomicAdd(&ssum[0][i2], x0); atomicAdd(&ssum[1][i2], x1); atomicAdd(&ssum[2][i2], x2);
    __syncthreads();
    if (tid < Mm)   atomicAdd(&g_cnt[b*Mm+tid], scnt[tid]);
    if (tid < 3*Mm) { int c = tid/Mm, m = tid%Mm; atomicAdd(&g_sum[(b*3+c)*Mm+m], ssum[c][m]); }
}

// ---------------- mean + KNN center (single block) --------------------------
__global__ void k_meancenter(const int* __restrict__ I) {
    int tid = threadIdx.x;
    for (int i = tid; i < Bb*3*Mm; i += blockDim.x) {
        int m = i % Mm; int b = (i/Mm)/3;
        g_cmean[i] = g_sum[i] / (g_cnt[b*Mm+m] + EPSF);
    }
    __syncthreads();
    for (int i = tid; i < Bb*3*Mm; i += blockDim.x) {
        int m = i % Mm; int bc = i / Mm; int b = bc/3; int c = bc%3;
        float s = 0.f;
        #pragma unroll
        for (int kk = 0; kk < SOMK; kk++) {
            int im = I[(b*Mm+m)*SOMK + kk];
            s += g_cmean[(b*3+c)*Mm + im];
        }
        g_center[i] = s * (1.0f/SOMK);
    }
}

// ---------------- fused layer-0: 2 points/thread, half2 stores -------------
__global__ void k_l0(const float* __restrict__ x, const float* __restrict__ sn,
                     const float* __restrict__ w0, const float* __restrict__ b0) {
    __shared__ float sw[64*6];
    __shared__ float sb[64];
    int tid = threadIdx.x;
    for (int i = tid; i < 64*6; i += blockDim.x) sw[i] = w0[i];
    if (tid < 64) sb[tid] = b0[tid];
    __syncthreads();
    int p = (blockIdx.x*blockDim.x + tid) * 2;
    int n = p % Nn; int b = p / KN;
    int nm0 = g_seg[p] % Mm, nm1 = g_seg[p+1] % Mm;
    float inA[6], inB[6];
    #pragma unroll
    for (int c = 0; c < 3; c++) {
        float2 xv = *(const float2*)&x[(b*3+c)*Nn+n];
        float2 sv = *(const float2*)&sn[(b*3+c)*Nn+n];
        inA[c]   = xv.x - g_cmean[(b*3+c)*Mm+nm0];
        inB[c]   = xv.y - g_cmean[(b*3+c)*Mm+nm1];
        inA[3+c] = sv.x;
        inB[3+c] = sv.y;
    }
    #pragma unroll
    for (int o = 0; o < 64; o++) {
        float a0 = sb[o], a1 = sb[o];
        #pragma unroll
        for (int c = 0; c < 6; c++) { a0 += sw[o*6+c]*inA[c]; a1 += sw[o*6+c]*inB[c]; }
        *(__half2*)&g_h02[(size_t)o*PTOT + p] =
            __floats2half2_rn(fmaxf(a0, 0.f), fmaxf(a1, 0.f));
    }
}

// ---------------- fp16 HMMA GEMM, BK=64, flattened (nx,t) pipeline ----------
// MW = warps along M (4 -> 128-row tile, 2 -> 64, 1 -> 32).
// OUT=0: fp16 C; OUT=2: smem segment-max + flush (MW=4); OUT=3: atomicMax out.
template<int OUT, int NX, int MW>
__global__ __launch_bounds__(256, 2)
void k_hgemm(const __half* __restrict__ A, const __half* __restrict__ Bm,
             const float* __restrict__ bias, void* __restrict__ C,
             int Nd, int Kd) {
    constexpr int MROWS = MW*32;
    constexpr int NW    = 8/MW;
    constexpr int NPW   = 128/NW;
    constexpr int NTC   = NPW/8;
    constexpr int ASB   = MROWS*APITCH*2;

    extern __shared__ __align__(1024) char dsm[];
    const uint32_t base = smem_u32(dsm);
    const uint32_t sA[2] = { base,           base + ASB };
    const uint32_t sB[2] = { base + 2*ASB,   base + 2*ASB + B_STG };
    float* smax = (float*)(dsm + SMEM_MW(4));

    const int tid  = threadIdx.x;
    const int lane = tid & 31, warp = tid >> 5;
    const int wm = warp % MW, wn = warp / MW;
    const int rowBase = blockIdx.x * MROWS;
    const int colBase = blockIdx.y * (128*NX);
    const int nT = Kd / 64;
    const int TT = NX * nT;
    const __half* Arow = A + (size_t)rowBase*Kd;

    if (OUT == 2) {
        for (int i = tid; i < 64*128; i += 256) smax[i] = 0.f;
        __syncthreads();
    }

    auto loadStage = [&](int nx, int t, int s) {
        #pragma unroll
        for (int i = 0; i < MW; i++) {
            int e = tid + i*256; int r = e >> 3, c = e & 7;
            CPA16(sA[s] + (uint32_t)(r*APITCH*2 + c*16),
                  (const char*)(Arow + (size_t)r*Kd + t*64 + c*8));
        }
        const __half* Brow = Bm + colBase + nx*128;
        #pragma unroll
        for (int i = 0; i < 4; i++) {
            int e = tid + i*256; int k = e >> 4, c = e & 15;
            uint32_t off = (uint32_t)(k*256 + c*16);
            off ^= ((uint32_t)(k & 7)) << 4;
            CPA16(sB[s] + off, (const char*)(Brow + (size_t)(t*64 + k)*Nd + c*8));
        }
    };

    float acc[2][NTC][4];
    #pragma unroll
    for (int i = 0; i < 2; i++)
        #pragma unroll
        for (int j = 0; j < NTC; j++)
            #pragma unroll
            for (int l = 0; l < 4; l++) acc[i][j][l] = 0.f;

    // flattened tile stream: (nx, t), continuously double-buffered
    loadStage(0, 0, 0); CPA_COMMIT();
    int nxL = 0, tL = 1;
    if (tL == nT) { tL = 0; nxL = 1; }
    int nxC = 0, tC = 0;
    for (int j = 0; j < TT; j++) {
        if (j + 1 < TT) {
            loadStage(nxL, tL, (j + 1) & 1); CPA_COMMIT(); CPA_WAIT(1);
            if (++tL == nT) { tL = 0; nxL++; }
        } else {
            CPA_WAIT(0);
        }
        __syncthreads();
        int buf = j & 1;
        #pragma unroll
        for (int ks = 0; ks < 4; ks++) {
            int kk = ks * 16;
            int mat = lane >> 3, r8 = lane & 7;
            uint32_t aF[2][4];
            #pragma unroll
            for (int mt = 0; mt < 2; mt++) {
                int row = wm*32 + mt*16 + r8 + ((mat & 1) << 3);
                int kof = kk + ((mat >> 1) << 3);
                LDSM4(aF[mt][0], aF[mt][1], aF[mt][2], aF[mt][3],
                      sA[buf] + (uint32_t)(row*APITCH*2 + kof*2));
            }
            uint32_t bF[MW][4];
            #pragma unroll
            for (int q = 0; q < MW; q++) {
                int k = kk + r8 + ((mat & 1) << 3);
                int n = wn*NPW + q*16 + ((mat >> 1) << 3);
                uint32_t off = (uint32_t)(k*256 + n*2);
                off ^= ((uint32_t)(k & 7)) << 4;
                LDSM4T(bF[q][0], bF[q][1], bF[q][2], bF[q][3], sB[buf] + off);
            }
            #pragma unroll
            for (int nt = 0; nt < NTC; nt++) {
                uint32_t b0 = bF[nt >> 1][(nt & 1)*2];
                uint32_t b1 = bF[nt >> 1][(nt & 1)*2 + 1];
                #pragma unroll
                for (int mt = 0; mt < 2; mt++)
                    mma16816(acc[mt][nt], aF[mt][0], aF[mt][1], aF[mt][2], aF[mt][3], b0, b1);
            }
        }

        if (tC == nT - 1) {
            // epilogue for column tile nxC (overlaps next tile's cp.async)
            const int cb = colBase + nxC*128;
            #pragma unroll
            for (int mt = 0; mt < 2; mt++) {
                int lr0 = wm*32 + mt*16 + (lane >> 2);
                int r0 = rowBase + lr0;
                float bv0 = bias[r0], bv1 = bias[r0 + 8];
                #pragma unroll
                for (int nt = 0; nt < NTC; nt++) {
                    int n0 = cb + wn*NPW + nt*8 + 2*(lane & 3);
                    float v00 = fmaxf(acc[mt][nt][0] + bv0, 0.f);
                    float v01 = fmaxf(acc[mt][nt][1] + bv0, 0.f);
                    float v10 = fmaxf(acc[mt][nt][2] + bv1, 0.f);
                    float v11 = fmaxf(acc[mt][nt][3] + bv1, 0.f);
                    if (OUT == 0) {
                        __half* Ch = (__half*)C;
                        *(__half2*)&Ch[(size_t)r0*Nd + n0]       = __floats2half2_rn(v00, v01);
                        *(__half2*)&Ch[(size_t)(r0 + 8)*Nd + n0] = __floats2half2_rn(v10, v11);
                    } else if (OUT == 3) {
                        float* Of = (float*)C;
                        atomicMax((int*)&Of[(n0 >> 6)*1024 + r0],         __float_as_int(v00));
                        atomicMax((int*)&Of[((n0+1) >> 6)*1024 + r0],     __float_as_int(v01));
                        atomicMax((int*)&Of[(n0 >> 6)*1024 + r0 + 8],     __float_as_int(v10));
                        atomicMax((int*)&Of[((n0+1) >> 6)*1024 + r0 + 8], __float_as_int(v11));
                    } else {
                        int s0 = g_seg[n0] & 63, s1 = g_seg[n0 + 1] & 63;
                        atomicMax((int*)&smax[s0*128 + lr0],     __float_as_int(v00));
                        atomicMax((int*)&smax[s1*128 + lr0],     __float_as_int(v01));
                        atomicMax((int*)&smax[s0*128 + lr0 + 8], __float_as_int(v10));
                        atomicMax((int*)&smax[s1*128 + lr0 + 8], __float_as_int(v11));
                        if ((n0 % KN) == 0) {
                            g_first0[(n0/KN)*384 + r0]     = v00;
                            g_first0[(n0/KN)*384 + r0 + 8] = v10;
                        }
                    }
                }
            }
            #pragma unroll
            for (int i = 0; i < 2; i++)
                #pragma unroll
                for (int jj = 0; jj < NTC; jj++)
                    #pragma unroll
                    for (int l = 0; l < 4; l++) acc[i][jj][l] = 0.f;
            tC = 0; nxC++;
        } else {
            tC++;
        }
        __syncthreads();
    }

    if (OUT == 2) {
        int bIdx = colBase / KN;
        for (int i = tid; i < 64*128; i += 256) {
            float v = smax[i];
            if (v > 0.f) {
                int node = i >> 7, lr = i & 127;
                atomicMax((int*)&g_nodeMax[(size_t)(bIdx*Mm + node)*384 + rowBase + lr],
                          __float_as_int(v));
            }
        }
    }
}

// ---------------- KNN module prep ------------------------------------------
__global__ void k_aug(const int* __restrict__ I) {
    int t = blockIdx.x*blockDim.x + threadIdx.x;
    if (t >= K_AUG*QTOT) return;
    int q = t % QTOT, c = t / QTOT;
    float v = 0.f;
    if (c < 387) {
        int kk = q % SOMK; int bm = q / SOMK; int b = bm / Mm; int m = bm % Mm;
        int im = I[bm*SOMK + kk];
        if (c < 3)
            v = g_cmean[(b*3+c)*Mm + im] - g_center[(b*3+c)*Mm + m];
        else
            v = (g_cnt[b*Mm+im] > 0.f) ? g_nodeMax[(size_t)(b*Mm+im)*384 + (c-3)]
                                       : g_first0[b*384 + (c-3)];
    }
    g_aug[t] = __float2half_rn(v);
}

__global__ void k_finin() {
    int t = blockIdx.x*blockDim.x + threadIdx.x;
    if (t >= K_FIN*RTOT) return;
    int r = t % RTOT, c = t / RTOT;
    float v = 0.f;
    if (c < 3) {
        int b = r / Mm, m = r % Mm;
        v = g_center[(b*3+c)*Mm + m];
    } else if (c < 515) {
        float mx = -1e30f;
        size_t base = (size_t)(c-3)*QTOT + (size_t)r*SOMK;
        #pragma unroll
        for (int kk = 0; kk < SOMK; kk++) mx = fmaxf(mx, __half2float(g_g2[base+kk]));
        v = mx;
    }
    g_finin[t] = __float2half_rn(v);
}

// ---------------- launch ----------------------------------------------------
extern "C" void kernel_launch(void* const* d_in, const int* in_sizes, int n_in,
                              void* d_out, int out_size) {
    const float* x      = (const float*)d_in[0];
    const float* sn     = (const float*)d_in[1];
    const float* node   = (const float*)d_in[2];
    const int*   knnI   = (const int*)  d_in[3];
    const float* pr_w0  = (const float*)d_in[4];
    const float* pr_b0  = (const float*)d_in[5];
    const float* pr_b1  = (const float*)d_in[7];
    const float* pr_b2  = (const float*)d_in[9];
    const float* pr_b3  = (const float*)d_in[11];
    const float* knn_b0 = (const float*)d_in[13];
    const float* knn_b1 = (const float*)d_in[15];
    const float* fin_b0 = (const float*)d_in[17];
    const float* fin_b1 = (const float*)d_in[19];
    float* out = (float*)d_out;

    __half *p_h02, *p_h1, *p_aug, *p_g1, *p_g2, *p_finin, *p_f1;
    __half *p_w1, *p_w2, *p_w3, *p_kw0, *p_kw1, *p_fw0, *p_fw1;
    cudaGetSymbolAddress((void**)&p_h02,   g_h02);
    cudaGetSymbolAddress((void**)&p_h1,    g_h1);
    cudaGetSymbolAddress((void**)&p_aug,   g_aug);
    cudaGetSymbolAddress((void**)&p_g1,    g_g1);
    cudaGetSymbolAddress((void**)&p_g2,    g_g2);
    cudaGetSymbolAddress((void**)&p_finin, g_finin);
    cudaGetSymbolAddress((void**)&p_f1,    g_f1);
    cudaGetSymbolAddress((void**)&p_w1,    g_w1);
    cudaGetSymbolAddress((void**)&p_w2,    g_w2);
    cudaGetSymbolAddress((void**)&p_w3,    g_w3);
    cudaGetSymbolAddress((void**)&p_kw0,   g_kw0);
    cudaGetSymbolAddress((void**)&p_kw1,   g_kw1);
    cudaGetSymbolAddress((void**)&p_fw0,   g_fw0);
    cudaGetSymbolAddress((void**)&p_fw1,   g_fw1);

    cudaFuncSetAttribute(k_hgemm<0,4,4>, cudaFuncAttributeMaxDynamicSharedMemorySize, SMEM_MW(4));
    cudaFuncSetAttribute(k_hgemm<0,2,4>, cudaFuncAttributeMaxDynamicSharedMemorySize, SMEM_MW(4));
    cudaFuncSetAttribute(k_hgemm<2,4,4>, cudaFuncAttributeMaxDynamicSharedMemorySize, SMEM_SEG);
    cudaFuncSetAttribute(k_hgemm<0,1,2>, cudaFuncAttributeMaxDynamicSharedMemorySize, SMEM_MW(2));
    cudaFuncSetAttribute(k_hgemm<0,1,1>, cudaFuncAttributeMaxDynamicSharedMemorySize, SMEM_MW(1));
    cudaFuncSetAttribute(k_hgemm<3,1,1>, cudaFuncAttributeMaxDynamicSharedMemorySize, SMEM_MW(1));

    k_wprep<<<(PREP_TOT + 255)/256, 256>>>(
        (const float*)d_in[6], (const float*)d_in[8], (const float*)d_in[10],
        (const float*)d_in[12], (const float*)d_in[14],
        (const float*)d_in[16], (const float*)d_in[18], out);

    k_assign<<<dim3(Nn/256, Bb), 256>>>(x, node);
    k_meancenter<<<1, 512>>>(knnI);
    k_l0<<<PTOT/512, 256>>>(x, sn, pr_w0, pr_b0);

    // PointResNet (HMMA fp16, BK=64, flattened pipelines)
    k_hgemm<0,4,4><<<dim3(1, PTOT/512), 256, SMEM_MW(4)>>>(p_w1, p_h02, pr_b1, p_h1, PTOT, 64);
    k_hgemm<0,2,4><<<dim3(2, PTOT/256), 256, SMEM_MW(4)>>>(p_w2, p_h1,  pr_b2, p_h02 + (size_t)64*PTOT, PTOT, 128);
    k_hgemm<2,4,4><<<dim3(3, PTOT/512), 256, SMEM_SEG>>>(p_w3, p_h02, pr_b3, nullptr, PTOT, 320);

    // KNN module over SOM nodes (64-row tiles)
    k_aug<<<(K_AUG*QTOT + 255)/256, 256>>>(knnI);
    k_hgemm<0,1,2><<<dim3(8, QTOT/128), 256, SMEM_MW(2)>>>(p_kw0, p_aug, knn_b0, p_g1, QTOT, K_AUG);
    k_hgemm<0,1,2><<<dim3(8, QTOT/128), 256, SMEM_MW(2)>>>(p_kw1, p_g1,  knn_b1, p_g2, QTOT, 512);

    // final PointNet (32-row tiles); last GEMM max-pools directly into out
    k_finin<<<(K_FIN*RTOT + 255)/256, 256>>>();
    k_hgemm<0,1,1><<<dim3(24, RTOT/128), 256, SMEM_MW(1)>>>(p_fw0, p_finin, fin_b0, p_f1, RTOT, K_FIN);
    k_hgemm<3,1,1><<<dim3(32, RTOT/128), 256, SMEM_MW(1)>>>(p_fw1, p_f1,    fin_b1, out,  RTOT, 768);
}